// round 1
// baseline (speedup 1.0000x reference)
#include <cuda_runtime.h>
#include <cuda_bf16.h>
#include <cstdint>

// Problem constants
#define BB 2
#define CC 256
#define HW 16384
#define SS 256
#define TT 128
#define NH 8
#define DH 32
#define SCALE 0.17677669529663689f   // 32^-0.5
#define LN_EPS 1e-5f

// ---------------- scratch (device globals; no allocation allowed) ----------------
__device__ float g_xfT[(size_t)BB * HW * CC];   // layernormed x, pixel-major [b][n][c]
__device__ float g_qT [(size_t)BB * HW * CC];   // [b][n][o]
__device__ float g_kT [(size_t)BB * HW * CC];
__device__ float g_vT [(size_t)BB * HW * CC];
__device__ float g_sims[(size_t)BB * SS * TT];
__device__ int   g_idx [(size_t)BB * SS * TT];

// ---------------- LayerNorm: x (B,C,H,W) -> xfT (B,HW,C), per-pixel LN over C ----
__global__ void ln_kernel(const float* __restrict__ x,
                          const float* __restrict__ lnw,
                          const float* __restrict__ lnb) {
    __shared__ float tile[256][33];
    __shared__ float red_s[8][32], red_ss[8][32];
    __shared__ float s_mean[32], s_inv[32];

    int blk = blockIdx.x;            // 1024 blocks, 512 per batch
    int b   = blk >> 9;
    int n0  = (blk & 511) * 32;
    int tid = threadIdx.x;           // 256
    int tn  = tid & 31;
    int cg  = tid >> 5;              // warp id 0..7

    const float* xb = x + (size_t)b * CC * HW;

    // coalesced load: warp cg loads channel rows (r*8+cg)
#pragma unroll 8
    for (int r = 0; r < 32; r++) {
        int c = r * 8 + cg;
        tile[c][tn] = xb[(size_t)c * HW + n0 + tn];
    }
    __syncthreads();

    // per-pixel reduction over channels (8 partial groups of 32)
    float s = 0.f, ss = 0.f;
#pragma unroll 8
    for (int j = 0; j < 32; j++) {
        float v = tile[cg * 32 + j][tn];
        s += v; ss += v * v;
    }
    red_s[cg][tn] = s; red_ss[cg][tn] = ss;
    __syncthreads();
    if (cg == 0) {
        float S = 0.f, SSU = 0.f;
#pragma unroll
        for (int j = 0; j < 8; j++) { S += red_s[j][tn]; SSU += red_ss[j][tn]; }
        float m   = S * (1.0f / 256.0f);
        float var = SSU * (1.0f / 256.0f) - m * m;
        s_mean[tn] = m;
        s_inv[tn]  = rsqrtf(var + LN_EPS);
    }
    __syncthreads();

    float wv = lnw[tid], bv = lnb[tid];
    float* outb = g_xfT + (size_t)(b * HW + n0) * CC;
#pragma unroll 8
    for (int it = 0; it < 32; it++) {
        float v = tile[tid][it];   // bank (tid+it)%32, conflict-free
        outb[(size_t)it * CC + tid] = (v - s_mean[it]) * s_inv[it] * wv + bv;
    }
}

// ---------------- GEMM: C[m,o] = sum_c xfT[m,c] * W[o,c]  (M=65536 total? no: M=B*HW=32768)
// BM=128, BN=64, BK=16, 256 threads, 8x4 microtile.
__global__ void gemm_kernel(const float* __restrict__ Wq,
                            const float* __restrict__ Wk,
                            const float* __restrict__ Wv) {
    __shared__ float As[16][129];  // [kk][m]
    __shared__ float Bs[16][65];   // [kk][o]

    int mat = blockIdx.z;
    const float* W = (mat == 0) ? Wq : ((mat == 1) ? Wk : Wv);
    float* Cout    = (mat == 0) ? g_qT : ((mat == 1) ? g_kT : g_vT);
    const float* A = g_xfT;

    int bm = blockIdx.x * 128;
    int bo = blockIdx.y * 64;
    int tid = threadIdx.x;
    int tx = tid & 15, ty = tid >> 4;
    int lc = tid & 15, lr = tid >> 4;

    float acc[8][4];
#pragma unroll
    for (int i = 0; i < 8; i++)
#pragma unroll
        for (int j = 0; j < 4; j++) acc[i][j] = 0.f;

    for (int kt = 0; kt < 256; kt += 16) {
#pragma unroll
        for (int r = 0; r < 8; r++)
            As[lc][lr + 16 * r] = A[(size_t)(bm + lr + 16 * r) * 256 + kt + lc];
#pragma unroll
        for (int r = 0; r < 4; r++)
            Bs[lc][lr + 16 * r] = W[(size_t)(bo + lr + 16 * r) * 256 + kt + lc];
        __syncthreads();
#pragma unroll
        for (int kk = 0; kk < 16; kk++) {
            float a[8], w[4];
#pragma unroll
            for (int i = 0; i < 8; i++) a[i] = As[kk][ty + 16 * i];
#pragma unroll
            for (int j = 0; j < 4; j++) w[j] = Bs[kk][tx + 16 * j];
#pragma unroll
            for (int i = 0; i < 8; i++)
#pragma unroll
                for (int j = 0; j < 4; j++) acc[i][j] += a[i] * w[j];
        }
        __syncthreads();
    }
#pragma unroll
    for (int i = 0; i < 8; i++) {
        size_t ro = (size_t)(bm + ty + 16 * i) * 256 + bo;
#pragma unroll
        for (int j = 0; j < 4; j++) Cout[ro + tx + 16 * j] = acc[i][j];
    }
}

// ---------------- top-k: per (b,s) row of 16384, select top-128 (radix select) ----
#define TK_N 16384
#define TOPK_SMEM ((TK_N + 256) * 4)
__global__ void topk_kernel(const float* __restrict__ aff) {
    extern __shared__ unsigned int shm[];
    unsigned int* keys = shm;           // 16384
    unsigned int* hist = shm + TK_N;    // 256
    __shared__ unsigned int s_prefix, s_rem, s_cntgt, s_cnteq;
    __shared__ int eq_idx[128];

    int row = blockIdx.x;                     // b*256 + s
    const float* ap = aff + (size_t)row * TK_N;
    int tid = threadIdx.x;                    // 256

    for (int n = tid; n < TK_N; n += 256) {
        unsigned int u = __float_as_uint(ap[n]);
        keys[n] = (u & 0x80000000u) ? ~u : (u | 0x80000000u);
    }
    if (tid == 0) { s_prefix = 0u; s_rem = 128u; s_cntgt = 0u; s_cnteq = 0u; }
    __syncthreads();

    for (int sh = 24; sh >= 0; sh -= 8) {
        hist[tid & 255] = 0u;
        __syncthreads();
        unsigned int pref = s_prefix;
        unsigned int mask = (sh == 24) ? 0u : (0xFFFFFFFFu << (sh + 8));
        for (int n = tid; n < TK_N; n += 256) {
            unsigned int k = keys[n];
            if (((k ^ pref) & mask) == 0u)
                atomicAdd(&hist[(k >> sh) & 0xFF], 1u);
        }
        __syncthreads();
        if (tid == 0) {
            unsigned int rem = s_rem, cum = 0u; int sel = 0;
            for (int bin = 255; bin >= 0; --bin) {
                unsigned int c = hist[bin];
                if (cum + c >= rem) { sel = bin; break; }
                cum += c;
            }
            s_prefix = pref | ((unsigned int)sel << sh);
            s_rem = rem - cum;
        }
        __syncthreads();
    }

    unsigned int thr = s_prefix;
    int take_eq = (int)s_rem;
    int n_gt = 128 - take_eq;

    for (int n = tid; n < TK_N; n += 256) {
        unsigned int k = keys[n];
        if (k > thr) {
            int p = (int)atomicAdd(&s_cntgt, 1u);
            g_idx[(size_t)row * 128 + p]  = n;
            g_sims[(size_t)row * 128 + p] = ap[n];
        } else if (k == thr) {
            int e = (int)atomicAdd(&s_cnteq, 1u);
            if (e < 128) eq_idx[e] = n;
        }
    }
    __syncthreads();
    if (tid == 0) {
        int ne = (int)s_cnteq; if (ne > 128) ne = 128;
        // sort ascending so ties break toward lowest index (matches lax.top_k)
        for (int i = 1; i < ne; i++) {
            int v = eq_idx[i]; int j = i - 1;
            while (j >= 0 && eq_idx[j] > v) { eq_idx[j + 1] = eq_idx[j]; j--; }
            eq_idx[j + 1] = v;
        }
        for (int i = 0; i < take_eq; i++) {
            int src = (i < ne) ? i : (ne - 1);        // defensive (ne>=1 always)
            int n = eq_idx[src];
            g_idx[(size_t)row * 128 + n_gt + i]  = n;
            g_sims[(size_t)row * 128 + n_gt + i] = ap[n];
        }
    }
}

// ---------------- init: out[b,c,n] = vT[b,n,c] (tiled transpose) ----------------
__global__ void init_out_kernel(float* __restrict__ out) {
    __shared__ float t[32][33];
    int n0 = blockIdx.x * 32, c0 = blockIdx.y * 32, b = blockIdx.z;
    int tx = threadIdx.x, ty = threadIdx.y;  // 32 x 8
    const float* vb = g_vT + (size_t)b * HW * CC;
#pragma unroll
    for (int j = ty; j < 32; j += 8)
        t[j][tx] = vb[(size_t)(n0 + j) * CC + c0 + tx];
    __syncthreads();
    float* ob = out + (size_t)b * CC * HW;
#pragma unroll
    for (int j = ty; j < 32; j += 8)
        ob[(size_t)(c0 + j) * HW + n0 + tx] = t[tx][j];
}

// ---------------- attention per (head, s, b): 128x128x32 + softmax + 128x32x128 --
#define ATTN_SMEM ((32*129 + 32*129 + 128*33 + 128*129 + 128 + 128 + 128) * 4)
__global__ void attn_kernel(float* __restrict__ res) {
    extern __shared__ float sm[];
    float* qT_s   = sm;                 // [32][129] (kk-major)
    float* kT_s   = qT_s + 32 * 129;
    float* vw_s   = kT_s + 32 * 129;    // [128][33] (row-major)
    float* sc     = vw_s + 128 * 33;    // [128][129]
    float* sims_s = sc + 128 * 129;
    float* rowsc  = sims_s + 128;
    int*   idx_s  = (int*)(rowsc + 128);

    int h = blockIdx.x, s = blockIdx.y, b = blockIdx.z;
    int tid = threadIdx.x;              // 256
    int base = ((b << 8) + s) << 7;

    if (tid < 128) {
        idx_s[tid]  = g_idx[base + tid];
        sims_s[tid] = g_sims[base + tid];
    }
    __syncthreads();

    int coff = h * DH;
    for (int i = tid; i < 4096; i += 256) {
        int u = i >> 5, c = i & 31;
        size_t off = ((size_t)(b * HW + idx_s[u])) * 256 + coff + c;
        qT_s[c * 129 + u] = g_qT[off];
        kT_s[c * 129 + u] = g_kT[off];
        vw_s[u * 33 + c]  = g_vT[off] * sims_s[u];
    }
    __syncthreads();

    // scores: S[r][c] = SCALE * sum_kk q[r][kk] * k[c][kk]  (8x8 microtile)
    {
        int tx = tid & 15, ty = tid >> 4;
        float acc[8][8];
#pragma unroll
        for (int i = 0; i < 8; i++)
#pragma unroll
            for (int j = 0; j < 8; j++) acc[i][j] = 0.f;
#pragma unroll
        for (int kk = 0; kk < 32; kk++) {
            float a[8], kb[8];
#pragma unroll
            for (int i = 0; i < 8; i++) a[i] = qT_s[kk * 129 + ty + 16 * i];
#pragma unroll
            for (int j = 0; j < 8; j++) kb[j] = kT_s[kk * 129 + tx + 16 * j];
#pragma unroll
            for (int i = 0; i < 8; i++)
#pragma unroll
                for (int j = 0; j < 8; j++) acc[i][j] += a[i] * kb[j];
        }
#pragma unroll
        for (int i = 0; i < 8; i++)
#pragma unroll
            for (int j = 0; j < 8; j++)
                sc[(ty + 16 * i) * 129 + tx + 16 * j] = acc[i][j] * SCALE;
    }
    __syncthreads();

    // softmax per row (unnormalized exp stored; norm folded into rowsc)
    if (tid < 128) {
        float* r = sc + tid * 129;
        float mx = -3.4e38f;
#pragma unroll 8
        for (int u = 0; u < 128; u++) mx = fmaxf(mx, r[u]);
        float sum = 0.f;
#pragma unroll 8
        for (int u = 0; u < 128; u++) {
            float e = __expf(r[u] - mx);
            sum += e; r[u] = e;
        }
        rowsc[tid] = sims_s[tid] / sum;
    }
    __syncthreads();

    // out: O[r][c] = sum_u P[r][u] * vw[u][c]   (4x4 microtile), then scale + scatter
    {
        int tx2 = tid & 7, ty2 = tid >> 3;   // tx2 0..7 (cols), ty2 0..31 (rows)
        float o[4][4];
#pragma unroll
        for (int i = 0; i < 4; i++)
#pragma unroll
            for (int j = 0; j < 4; j++) o[i][j] = 0.f;
#pragma unroll 4
        for (int u = 0; u < 128; u++) {
            float p[4], v[4];
#pragma unroll
            for (int i = 0; i < 4; i++) p[i] = sc[(ty2 + 32 * i) * 129 + u];
#pragma unroll
            for (int j = 0; j < 4; j++) v[j] = vw_s[u * 33 + tx2 + 8 * j];
#pragma unroll
            for (int i = 0; i < 4; i++)
#pragma unroll
                for (int j = 0; j < 4; j++) o[i][j] += p[i] * v[j];
        }
#pragma unroll
        for (int i = 0; i < 4; i++) {
            int r = ty2 + 32 * i;
            float rs = rowsc[r];
            int n = idx_s[r];
            float* rp = res + ((size_t)b * CC + coff) * HW + n;
#pragma unroll
            for (int j = 0; j < 4; j++) {
                int c = tx2 + 8 * j;
                atomicAdd(rp + (size_t)c * HW, o[i][j] * rs);
            }
        }
    }
}

// ---------------- launch ----------------
extern "C" void kernel_launch(void* const* d_in, const int* in_sizes, int n_in,
                              void* d_out, int out_size) {
    const float* x   = (const float*)d_in[0];
    const float* aff = (const float*)d_in[1];
    const float* lnw = (const float*)d_in[2];
    const float* lnb = (const float*)d_in[3];
    const float* wq  = (const float*)d_in[4];
    const float* wk  = (const float*)d_in[5];
    const float* wv  = (const float*)d_in[6];
    float* out = (float*)d_out;

    cudaFuncSetAttribute(topk_kernel, cudaFuncAttributeMaxDynamicSharedMemorySize, TOPK_SMEM);
    cudaFuncSetAttribute(attn_kernel, cudaFuncAttributeMaxDynamicSharedMemorySize, ATTN_SMEM);

    ln_kernel<<<1024, 256>>>(x, lnw, lnb);
    gemm_kernel<<<dim3(256, 4, 3), 256>>>(wq, wk, wv);
    topk_kernel<<<BB * SS, 256, TOPK_SMEM>>>(aff);
    init_out_kernel<<<dim3(HW / 32, CC / 32, BB), dim3(32, 8)>>>(out);
    attn_kernel<<<dim3(NH, SS, BB), 256, ATTN_SMEM>>>(out);
}

// round 2
// speedup vs baseline: 1.0276x; 1.0276x over previous
#include <cuda_runtime.h>
#include <cuda_bf16.h>
#include <cstdint>

// Problem constants
#define BB 2
#define CC 256
#define HW 16384
#define SS 256
#define TT 128
#define NH 8
#define DH 32
#define SCALE 0.17677669529663689f   // 32^-0.5
#define LN_EPS 1e-5f

typedef unsigned long long u64;

// packed fp32x2 FMA (Blackwell FFMA2) — acc = a*b + acc, lanewise on 2 floats
#define FFMA2(acc, a, b) asm("fma.rn.f32x2 %0, %1, %2, %0;" : "+l"(acc) : "l"(a), "l"(b))

__device__ __forceinline__ float f2lo(u64 v) { return __uint_as_float((unsigned)v); }
__device__ __forceinline__ float f2hi(u64 v) { return __uint_as_float((unsigned)(v >> 32)); }

// ---------------- scratch (device globals; no allocation allowed) ----------------
__device__ float g_xfT[(size_t)BB * HW * CC];   // layernormed x, pixel-major [b][n][c]
__device__ float g_qT [(size_t)BB * HW * CC];   // [b][n][o]
__device__ float g_kT [(size_t)BB * HW * CC];
__device__ float g_vT [(size_t)BB * HW * CC];
__device__ float g_sims[(size_t)BB * SS * TT];
__device__ int   g_idx [(size_t)BB * SS * TT];

// ---------------- LayerNorm: x (B,C,H,W) -> xfT (B,HW,C), per-pixel LN over C ----
__global__ void ln_kernel(const float* __restrict__ x,
                          const float* __restrict__ lnw,
                          const float* __restrict__ lnb) {
    __shared__ float tile[256][33];
    __shared__ float red_s[8][32], red_ss[8][32];
    __shared__ float s_mean[32], s_inv[32];

    int blk = blockIdx.x;            // 1024 blocks, 512 per batch
    int b   = blk >> 9;
    int n0  = (blk & 511) * 32;
    int tid = threadIdx.x;           // 256
    int tn  = tid & 31;
    int cg  = tid >> 5;              // warp id 0..7

    const float* xb = x + (size_t)b * CC * HW;

#pragma unroll 8
    for (int r = 0; r < 32; r++) {
        int c = r * 8 + cg;
        tile[c][tn] = xb[(size_t)c * HW + n0 + tn];
    }
    __syncthreads();

    float s = 0.f, ss = 0.f;
#pragma unroll 8
    for (int j = 0; j < 32; j++) {
        float v = tile[cg * 32 + j][tn];
        s += v; ss += v * v;
    }
    red_s[cg][tn] = s; red_ss[cg][tn] = ss;
    __syncthreads();
    if (cg == 0) {
        float S = 0.f, SSU = 0.f;
#pragma unroll
        for (int j = 0; j < 8; j++) { S += red_s[j][tn]; SSU += red_ss[j][tn]; }
        float m   = S * (1.0f / 256.0f);
        float var = SSU * (1.0f / 256.0f) - m * m;
        s_mean[tn] = m;
        s_inv[tn]  = rsqrtf(var + LN_EPS);
    }
    __syncthreads();

    float wv = lnw[tid], bv = lnb[tid];
    float* outb = g_xfT + (size_t)(b * HW + n0) * CC;
#pragma unroll 8
    for (int it = 0; it < 32; it++) {
        float v = tile[tid][it];
        outb[(size_t)it * CC + tid] = (v - s_mean[it]) * s_inv[it] * wv + bv;
    }
}

// ---------------- GEMM: C[m,o] = sum_c xfT[m,c] * W[o,c]
// BM=128, BN=128, BK=16, 256 threads, 8x8 microtile, FFMA2 row-pair packing.
__global__ void gemm_kernel(const float* __restrict__ Wq,
                            const float* __restrict__ Wk,
                            const float* __restrict__ Wv) {
    __shared__ float  As[16][130];     // [kk][m], even row stride -> float2 aligned
    __shared__ float2 Bd[16][130];     // [kk][o] duplicated {w,w}

    int mat = blockIdx.z;
    const float* W = (mat == 0) ? Wq : ((mat == 1) ? Wk : Wv);
    float* Cout    = (mat == 0) ? g_qT : ((mat == 1) ? g_kT : g_vT);
    const float* A = g_xfT;

    int bm = blockIdx.x * 128;
    int bo = blockIdx.y * 128;
    int tid = threadIdx.x;
    int tx = tid & 15, ty = tid >> 4;     // cols tx+16j, row pairs 2ty+32i
    int lc = tid & 15, lr = tid >> 4;

    u64 acc[4][8];
#pragma unroll
    for (int i = 0; i < 4; i++)
#pragma unroll
        for (int j = 0; j < 8; j++) acc[i][j] = 0ull;

    for (int kt = 0; kt < 256; kt += 16) {
#pragma unroll
        for (int r = 0; r < 8; r++)
            As[lc][lr + 16 * r] = A[(size_t)(bm + lr + 16 * r) * 256 + kt + lc];
#pragma unroll
        for (int r = 0; r < 8; r++) {
            float w = W[(size_t)(bo + lr + 16 * r) * 256 + kt + lc];
            Bd[lc][lr + 16 * r] = make_float2(w, w);
        }
        __syncthreads();
#pragma unroll
        for (int kk = 0; kk < 16; kk++) {
            u64 ap[4], wd[8];
#pragma unroll
            for (int i = 0; i < 4; i++)
                ap[i] = *(const u64*)&As[kk][2 * ty + 32 * i];
#pragma unroll
            for (int j = 0; j < 8; j++)
                wd[j] = *(const u64*)&Bd[kk][tx + 16 * j];
#pragma unroll
            for (int i = 0; i < 4; i++)
#pragma unroll
                for (int j = 0; j < 8; j++) FFMA2(acc[i][j], ap[i], wd[j]);
        }
        __syncthreads();
    }
#pragma unroll
    for (int i = 0; i < 4; i++) {
        size_t r0 = (size_t)(bm + 2 * ty + 32 * i) * 256 + bo;
#pragma unroll
        for (int j = 0; j < 8; j++) {
            Cout[r0 + tx + 16 * j]       = f2lo(acc[i][j]);
            Cout[r0 + 256 + tx + 16 * j] = f2hi(acc[i][j]);
        }
    }
}

// ---------------- top-k: per (b,s) row of 16384, select top-128 (radix select) ----
#define TK_N 16384
#define TOPK_SMEM ((TK_N + 256) * 4)
__global__ void topk_kernel(const float* __restrict__ aff) {
    extern __shared__ unsigned int shm[];
    unsigned int* keys = shm;           // 16384
    unsigned int* hist = shm + TK_N;    // 256
    __shared__ unsigned int s_prefix, s_rem, s_cntgt, s_cnteq;
    __shared__ int eq_idx[128];

    int row = blockIdx.x;
    const float* ap = aff + (size_t)row * TK_N;
    int tid = threadIdx.x;              // 256

    for (int n = tid; n < TK_N; n += 256) {
        unsigned int u = __float_as_uint(ap[n]);
        keys[n] = (u & 0x80000000u) ? ~u : (u | 0x80000000u);
    }
    if (tid == 0) { s_prefix = 0u; s_rem = 128u; s_cntgt = 0u; s_cnteq = 0u; }
    __syncthreads();

    for (int sh = 24; sh >= 0; sh -= 8) {
        hist[tid & 255] = 0u;
        __syncthreads();
        unsigned int pref = s_prefix;
        unsigned int mask = (sh == 24) ? 0u : (0xFFFFFFFFu << (sh + 8));
        for (int n = tid; n < TK_N; n += 256) {
            unsigned int k = keys[n];
            if (((k ^ pref) & mask) == 0u)
                atomicAdd(&hist[(k >> sh) & 0xFF], 1u);
        }
        __syncthreads();
        if (tid == 0) {
            unsigned int rem = s_rem, cum = 0u; int sel = 0;
            for (int bin = 255; bin >= 0; --bin) {
                unsigned int c = hist[bin];
                if (cum + c >= rem) { sel = bin; break; }
                cum += c;
            }
            s_prefix = pref | ((unsigned int)sel << sh);
            s_rem = rem - cum;
        }
        __syncthreads();
    }

    unsigned int thr = s_prefix;
    int take_eq = (int)s_rem;
    int n_gt = 128 - take_eq;

    for (int n = tid; n < TK_N; n += 256) {
        unsigned int k = keys[n];
        if (k > thr) {
            int p = (int)atomicAdd(&s_cntgt, 1u);
            g_idx[(size_t)row * 128 + p]  = n;
            g_sims[(size_t)row * 128 + p] = ap[n];
        } else if (k == thr) {
            int e = (int)atomicAdd(&s_cnteq, 1u);
            if (e < 128) eq_idx[e] = n;
        }
    }
    __syncthreads();
    if (tid == 0) {
        int ne = (int)s_cnteq; if (ne > 128) ne = 128;
        for (int i = 1; i < ne; i++) {
            int v = eq_idx[i]; int j = i - 1;
            while (j >= 0 && eq_idx[j] > v) { eq_idx[j + 1] = eq_idx[j]; j--; }
            eq_idx[j + 1] = v;
        }
        for (int i = 0; i < take_eq; i++) {
            int src = (i < ne) ? i : (ne - 1);
            int n = eq_idx[src];
            g_idx[(size_t)row * 128 + n_gt + i]  = n;
            g_sims[(size_t)row * 128 + n_gt + i] = ap[n];
        }
    }
}

// ---------------- init: out[b,c,n] = vT[b,n,c] (tiled transpose) ----------------
__global__ void init_out_kernel(float* __restrict__ out) {
    __shared__ float t[32][33];
    int n0 = blockIdx.x * 32, c0 = blockIdx.y * 32, b = blockIdx.z;
    int tx = threadIdx.x, ty = threadIdx.y;  // 32 x 8
    const float* vb = g_vT + (size_t)b * HW * CC;
#pragma unroll
    for (int j = ty; j < 32; j += 8)
        t[j][tx] = vb[(size_t)(n0 + j) * CC + c0 + tx];
    __syncthreads();
    float* ob = out + (size_t)b * CC * HW;
#pragma unroll
    for (int j = ty; j < 32; j += 8)
        ob[(size_t)(c0 + j) * HW + n0 + tx] = t[tx][j];
}

// ---------------- attention per (head, s, b) -------------------------------------
// smem: qT (SCALE folded) [32][130]f, kT dup [32][129]f2, vw dup [128][33]f2,
//       scT transposed [128][130]f, sims/rowsc/idx
#define ATTN_SMEM ((32*130 + 128*130 + 128*3) * 4 + (32*129 + 128*33) * 8)
__global__ void attn_kernel(float* __restrict__ res) {
    extern __shared__ float sm[];
    float*  qT_s   = sm;                            // [32][130] (kk-major), *SCALE
    float2* kT_d   = (float2*)(qT_s + 32 * 130);    // [32][129] dup
    float2* vw_d   = kT_d + 32 * 129;               // [128][33] dup
    float*  scT    = (float*)(vw_d + 128 * 33);     // [128][130]  scT[u][r]
    float*  sims_s = scT + 128 * 130;
    float*  rowsc  = sims_s + 128;
    int*    idx_s  = (int*)(rowsc + 128);

    int h = blockIdx.x, s = blockIdx.y, b = blockIdx.z;
    int tid = threadIdx.x;              // 256
    int base = ((b << 8) + s) << 7;

    if (tid < 128) {
        idx_s[tid]  = g_idx[base + tid];
        sims_s[tid] = g_sims[base + tid];
    }
    __syncthreads();

    int coff = h * DH;
    for (int i = tid; i < 4096; i += 256) {
        int u = i >> 5, c = i & 31;
        size_t off = ((size_t)(b * HW + idx_s[u])) * 256 + coff + c;
        qT_s[c * 130 + u] = g_qT[off] * SCALE;
        float kv = g_kT[off];
        kT_d[c * 129 + u] = make_float2(kv, kv);
        float vv = g_vT[off] * sims_s[u];
        vw_d[u * 33 + c] = make_float2(vv, vv);
    }
    __syncthreads();

    // scores: scT[c][r] = sum_kk q[r][kk]*k[c][kk]  (row-pair FFMA2, 8x8 micro)
    {
        int tx = tid & 15, ty = tid >> 4;
        u64 acc[4][8];
#pragma unroll
        for (int i = 0; i < 4; i++)
#pragma unroll
            for (int j = 0; j < 8; j++) acc[i][j] = 0ull;
#pragma unroll
        for (int kk = 0; kk < 32; kk++) {
            u64 qp[4], kd[8];
#pragma unroll
            for (int i = 0; i < 4; i++)
                qp[i] = *(const u64*)&qT_s[kk * 130 + 2 * ty + 32 * i];
#pragma unroll
            for (int j = 0; j < 8; j++)
                kd[j] = *(const u64*)&kT_d[kk * 129 + tx + 16 * j];
#pragma unroll
            for (int i = 0; i < 4; i++)
#pragma unroll
                for (int j = 0; j < 8; j++) FFMA2(acc[i][j], qp[i], kd[j]);
        }
#pragma unroll
        for (int j = 0; j < 8; j++) {
            int c = tx + 16 * j;
#pragma unroll
            for (int i = 0; i < 4; i++)
                *(u64*)&scT[c * 130 + 2 * ty + 32 * i] = acc[i][j];
        }
    }
    __syncthreads();

    // softmax per row r (scT column r), unnormalized exp; norm folded into rowsc
    if (tid < 128) {
        float mx = -3.4e38f;
#pragma unroll 8
        for (int u = 0; u < 128; u++) mx = fmaxf(mx, scT[u * 130 + tid]);
        float sum = 0.f;
#pragma unroll 8
        for (int u = 0; u < 128; u++) {
            float e = __expf(scT[u * 130 + tid] - mx);
            sum += e; scT[u * 130 + tid] = e;
        }
        rowsc[tid] = sims_s[tid] / sum;
    }
    __syncthreads();

    // out: O[r][c] = sum_u P[r][u]*vw[u][c]  (row-pair FFMA2), scale + scatter
    {
        int tx2 = tid & 7, ty2 = tid >> 3;   // cols tx2+8j, row pairs 2ty2+64ip
        u64 o[2][4];
#pragma unroll
        for (int i = 0; i < 2; i++)
#pragma unroll
            for (int j = 0; j < 4; j++) o[i][j] = 0ull;
#pragma unroll 4
        for (int u = 0; u < 128; u++) {
            u64 pp[2], vd[4];
#pragma unroll
            for (int i = 0; i < 2; i++)
                pp[i] = *(const u64*)&scT[u * 130 + 2 * ty2 + 64 * i];
#pragma unroll
            for (int j = 0; j < 4; j++)
                vd[j] = *(const u64*)&vw_d[u * 33 + tx2 + 8 * j];
#pragma unroll
            for (int i = 0; i < 2; i++)
#pragma unroll
                for (int j = 0; j < 4; j++) FFMA2(o[i][j], pp[i], vd[j]);
        }
#pragma unroll
        for (int i = 0; i < 2; i++) {
            int r0 = 2 * ty2 + 64 * i;
            float rs0 = rowsc[r0], rs1 = rowsc[r0 + 1];
            int n0 = idx_s[r0], n1 = idx_s[r0 + 1];
            float* rp = res + ((size_t)b * CC + coff) * HW;
#pragma unroll
            for (int j = 0; j < 4; j++) {
                int c = tx2 + 8 * j;
                atomicAdd(rp + (size_t)c * HW + n0, f2lo(o[i][j]) * rs0);
                atomicAdd(rp + (size_t)c * HW + n1, f2hi(o[i][j]) * rs1);
            }
        }
    }
}

// ---------------- launch ----------------
extern "C" void kernel_launch(void* const* d_in, const int* in_sizes, int n_in,
                              void* d_out, int out_size) {
    const float* x   = (const float*)d_in[0];
    const float* aff = (const float*)d_in[1];
    const float* lnw = (const float*)d_in[2];
    const float* lnb = (const float*)d_in[3];
    const float* wq  = (const float*)d_in[4];
    const float* wk  = (const float*)d_in[5];
    const float* wv  = (const float*)d_in[6];
    float* out = (float*)d_out;

    cudaFuncSetAttribute(topk_kernel, cudaFuncAttributeMaxDynamicSharedMemorySize, TOPK_SMEM);
    cudaFuncSetAttribute(attn_kernel, cudaFuncAttributeMaxDynamicSharedMemorySize, ATTN_SMEM);

    ln_kernel<<<1024, 256>>>(x, lnw, lnb);
    gemm_kernel<<<dim3(256, 2, 3), 256>>>(wq, wk, wv);
    topk_kernel<<<BB * SS, 256, TOPK_SMEM>>>(aff);
    init_out_kernel<<<dim3(HW / 32, CC / 32, BB), dim3(32, 8)>>>(out);
    attn_kernel<<<dim3(NH, SS, BB), 256, ATTN_SMEM>>>(out);
}

// round 7
// speedup vs baseline: 1.3872x; 1.3499x over previous
#include <cuda_runtime.h>
#include <cuda_bf16.h>
#include <cstdint>

// Problem constants
#define BB 2
#define CC 256
#define HW 16384
#define SS 256
#define TT 128
#define NH 8
#define DH 32
#define SCALE 0.17677669529663689f   // 32^-0.5
#define LN_EPS 1e-5f

typedef unsigned long long u64;

// packed fp32x2 FMA (Blackwell FFMA2) — acc = a*b + acc, lanewise on 2 floats
#define FFMA2(acc, a, b) asm("fma.rn.f32x2 %0, %1, %2, %0;" : "+l"(acc) : "l"(a), "l"(b))

__device__ __forceinline__ float f2lo(u64 v) { return __uint_as_float((unsigned)v); }
__device__ __forceinline__ float f2hi(u64 v) { return __uint_as_float((unsigned)(v >> 32)); }
// duplicate a float into both lanes of a packed f32x2 (register MOVs, alu pipe)
__device__ __forceinline__ u64 dupf(float v) {
    u64 r; asm("mov.b64 %0, {%1, %1};" : "=l"(r) : "f"(v)); return r;
}

// ---------------- scratch (device globals; no allocation allowed) ----------------
__device__ float g_xfT[(size_t)BB * HW * CC];   // layernormed x, pixel-major [b][n][c]
__device__ float g_qT [(size_t)BB * HW * CC];   // [b][n][o]
__device__ float g_kT [(size_t)BB * HW * CC];
__device__ float g_vT [(size_t)BB * HW * CC];
__device__ float g_sims[(size_t)BB * SS * TT];
__device__ int   g_idx [(size_t)BB * SS * TT];

// ---------------- LayerNorm: x (B,C,H,W) -> xfT (B,HW,C), per-pixel LN over C ----
__global__ void ln_kernel(const float* __restrict__ x,
                          const float* __restrict__ lnw,
                          const float* __restrict__ lnb) {
    __shared__ float tile[256][33];
    __shared__ float red_s[8][32], red_ss[8][32];
    __shared__ float s_mean[32], s_inv[32];

    int blk = blockIdx.x;            // 1024 blocks, 512 per batch
    int b   = blk >> 9;
    int n0  = (blk & 511) * 32;
    int tid = threadIdx.x;           // 256
    int tn  = tid & 31;
    int cg  = tid >> 5;              // warp id 0..7

    const float* xb = x + (size_t)b * CC * HW;

#pragma unroll 8
    for (int r = 0; r < 32; r++) {
        int c = r * 8 + cg;
        tile[c][tn] = xb[(size_t)c * HW + n0 + tn];
    }
    __syncthreads();

    float s = 0.f, ss = 0.f;
#pragma unroll 8
    for (int j = 0; j < 32; j++) {
        float v = tile[cg * 32 + j][tn];
        s += v; ss += v * v;
    }
    red_s[cg][tn] = s; red_ss[cg][tn] = ss;
    __syncthreads();
    if (cg == 0) {
        float S = 0.f, SSU = 0.f;
#pragma unroll
        for (int j = 0; j < 8; j++) { S += red_s[j][tn]; SSU += red_ss[j][tn]; }
        float m   = S * (1.0f / 256.0f);
        float var = SSU * (1.0f / 256.0f) - m * m;
        s_mean[tn] = m;
        s_inv[tn]  = rsqrtf(var + LN_EPS);
    }
    __syncthreads();

    float wv = lnw[tid], bv = lnb[tid];
    float* outb = g_xfT + (size_t)(b * HW + n0) * CC;
#pragma unroll 8
    for (int it = 0; it < 32; it++) {
        float v = tile[tid][it];
        outb[(size_t)it * CC + tid] = (v - s_mean[it]) * s_inv[it] * wv + bv;
    }
}

// ---------------- GEMM: C[m,o] = sum_c xfT[m,c] * W[o,c]
// BM=128, BN=128, BK=16, 256 threads. Microtile 8 rows x 8 cols (4 col-pairs).
// A duplicated in registers, B read as natural float2 pairs -> distinct bytes only.
__global__ void __launch_bounds__(256, 2) gemm_kernel(const float* __restrict__ Wq,
                            const float* __restrict__ Wk,
                            const float* __restrict__ Wv) {
    __shared__ float As[16][130];   // [kk][m]
    __shared__ float Bs[16][130];   // [kk][o]

    int mat = blockIdx.z;
    const float* W = (mat == 0) ? Wq : ((mat == 1) ? Wk : Wv);
    float* Cout    = (mat == 0) ? g_qT : ((mat == 1) ? g_kT : g_vT);
    const float* A = g_xfT;

    int bm = blockIdx.x * 128;
    int bo = blockIdx.y * 128;
    int tid = threadIdx.x;
    int tx = tid & 15, ty = tid >> 4;   // cols 2tx+32j (pairs), rows 8ty..8ty+7
    int lc = tid & 15, lr = tid >> 4;

    u64 acc[8][4];
#pragma unroll
    for (int i = 0; i < 8; i++)
#pragma unroll
        for (int j = 0; j < 4; j++) acc[i][j] = 0ull;

    for (int kt = 0; kt < 256; kt += 16) {
#pragma unroll
        for (int r = 0; r < 8; r++)
            As[lc][lr + 16 * r] = A[(size_t)(bm + lr + 16 * r) * 256 + kt + lc];
#pragma unroll
        for (int r = 0; r < 8; r++)
            Bs[lc][lr + 16 * r] = W[(size_t)(bo + lr + 16 * r) * 256 + kt + lc];
        __syncthreads();
#pragma unroll
        for (int kk = 0; kk < 16; kk++) {
            u64 ad[8], bp[4];
#pragma unroll
            for (int p = 0; p < 4; p++) {
                float2 a2 = *(const float2*)&As[kk][8 * ty + 2 * p];
                ad[2 * p]     = dupf(a2.x);
                ad[2 * p + 1] = dupf(a2.y);
            }
#pragma unroll
            for (int j = 0; j < 4; j++)
                bp[j] = *(const u64*)&Bs[kk][2 * tx + 32 * j];
#pragma unroll
            for (int i = 0; i < 8; i++)
#pragma unroll
                for (int j = 0; j < 4; j++) FFMA2(acc[i][j], ad[i], bp[j]);
        }
        __syncthreads();
    }
#pragma unroll
    for (int i = 0; i < 8; i++) {
        size_t r0 = (size_t)(bm + 8 * ty + i) * 256 + bo;
#pragma unroll
        for (int j = 0; j < 4; j++)
            *(float2*)&Cout[r0 + 2 * tx + 32 * j] = *(float2*)&acc[i][j];
    }
}

// ---------------- top-k: per (b,s) row of 16384, select top-128 (radix select) ----
#define TK_N 16384
#define TOPK_SMEM ((TK_N + 256) * 4)
__global__ void topk_kernel(const float* __restrict__ aff) {
    extern __shared__ unsigned int shm[];
    unsigned int* keys = shm;           // 16384
    unsigned int* hist = shm + TK_N;    // 256
    __shared__ unsigned int s_prefix, s_rem, s_cntgt, s_cnteq;
    __shared__ int eq_idx[128];

    int row = blockIdx.x;
    const float* ap = aff + (size_t)row * TK_N;
    int tid = threadIdx.x;              // 256

    for (int n = tid; n < TK_N; n += 256) {
        unsigned int u = __float_as_uint(ap[n]);
        keys[n] = (u & 0x80000000u) ? ~u : (u | 0x80000000u);
    }
    if (tid == 0) { s_prefix = 0u; s_rem = 128u; s_cntgt = 0u; s_cnteq = 0u; }
    __syncthreads();

    for (int sh = 24; sh >= 0; sh -= 8) {
        hist[tid & 255] = 0u;
        __syncthreads();
        unsigned int pref = s_prefix;
        unsigned int mask = (sh == 24) ? 0u : (0xFFFFFFFFu << (sh + 8));
        for (int n = tid; n < TK_N; n += 256) {
            unsigned int k = keys[n];
            if (((k ^ pref) & mask) == 0u)
                atomicAdd(&hist[(k >> sh) & 0xFF], 1u);
        }
        __syncthreads();
        if (tid == 0) {
            unsigned int rem = s_rem, cum = 0u; int sel = 0;
            for (int bin = 255; bin >= 0; --bin) {
                unsigned int c = hist[bin];
                if (cum + c >= rem) { sel = bin; break; }
                cum += c;
            }
            s_prefix = pref | ((unsigned int)sel << sh);
            s_rem = rem - cum;
        }
        __syncthreads();
    }

    unsigned int thr = s_prefix;
    int take_eq = (int)s_rem;
    int n_gt = 128 - take_eq;

    for (int n = tid; n < TK_N; n += 256) {
        unsigned int k = keys[n];
        if (k > thr) {
            int p = (int)atomicAdd(&s_cntgt, 1u);
            g_idx[(size_t)row * 128 + p]  = n;
            g_sims[(size_t)row * 128 + p] = ap[n];
        } else if (k == thr) {
            int e = (int)atomicAdd(&s_cnteq, 1u);
            if (e < 128) eq_idx[e] = n;
        }
    }
    __syncthreads();
    if (tid == 0) {
        int ne = (int)s_cnteq; if (ne > 128) ne = 128;
        for (int i = 1; i < ne; i++) {
            int v = eq_idx[i]; int j = i - 1;
            while (j >= 0 && eq_idx[j] > v) { eq_idx[j + 1] = eq_idx[j]; j--; }
            eq_idx[j + 1] = v;
        }
        for (int i = 0; i < take_eq; i++) {
            int src = (i < ne) ? i : (ne - 1);
            int n = eq_idx[src];
            g_idx[(size_t)row * 128 + n_gt + i]  = n;
            g_sims[(size_t)row * 128 + n_gt + i] = ap[n];
        }
    }
}

// ---------------- init: out[b,c,n] = vT[b,n,c] (tiled transpose) ----------------
__global__ void init_out_kernel(float* __restrict__ out) {
    __shared__ float t[32][33];
    int n0 = blockIdx.x * 32, c0 = blockIdx.y * 32, b = blockIdx.z;
    int tx = threadIdx.x, ty = threadIdx.y;  // 32 x 8
    const float* vb = g_vT + (size_t)b * HW * CC;
#pragma unroll
    for (int j = ty; j < 32; j += 8)
        t[j][tx] = vb[(size_t)(n0 + j) * CC + c0 + tx];
    __syncthreads();
    float* ob = out + (size_t)b * CC * HW;
#pragma unroll
    for (int j = ty; j < 32; j += 8)
        ob[(size_t)(c0 + j) * HW + n0 + tx] = t[tx][j];
}

// ---------------- attention per (head, s, b) -------------------------------------
// smem: qT [32][130] (*SCALE), kT [32][130], vw [128][36] (*sims),
//       scT [128][130] (scT[u][r]), sims/rowsc/idx
#define ATTN_SMEM ((32*130*2 + 128*36 + 128*130 + 128*3) * 4)
__global__ void __launch_bounds__(256, 1) attn_kernel(float* __restrict__ res) {
    extern __shared__ float sm[];
    float* qT_s   = sm;                     // [32][130] kk-major, *SCALE
    float* kT_s   = qT_s + 32 * 130;        // [32][130] kk-major
    float* vw_s   = kT_s + 32 * 130;        // [128][36] row-major, *sims
    float* scT    = vw_s + 128 * 36;        // [128][130]  scT[u][r]
    float* sims_s = scT + 128 * 130;
    float* rowsc  = sims_s + 128;
    int*   idx_s  = (int*)(rowsc + 128);

    int h = blockIdx.x, s = blockIdx.y, b = blockIdx.z;
    int tid = threadIdx.x;              // 256
    int base = ((b << 8) + s) << 7;

    if (tid < 128) {
        idx_s[tid]  = g_idx[base + tid];
        sims_s[tid] = g_sims[base + tid];
    }
    __syncthreads();

    int coff = h * DH;
    // gather with float4 (32 channels per u = 8 quads)
    for (int i = tid; i < 1024; i += 256) {
        int u = i >> 3, c = (i & 7) * 4;
        size_t off = ((size_t)(b * HW + idx_s[u])) * 256 + coff + c;
        float4 qv = *(const float4*)&g_qT[off];
        float4 kv = *(const float4*)&g_kT[off];
        float4 vv = *(const float4*)&g_vT[off];
        float sw = sims_s[u];
        qT_s[(c + 0) * 130 + u] = qv.x * SCALE;
        qT_s[(c + 1) * 130 + u] = qv.y * SCALE;
        qT_s[(c + 2) * 130 + u] = qv.z * SCALE;
        qT_s[(c + 3) * 130 + u] = qv.w * SCALE;
        kT_s[(c + 0) * 130 + u] = kv.x;
        kT_s[(c + 1) * 130 + u] = kv.y;
        kT_s[(c + 2) * 130 + u] = kv.z;
        kT_s[(c + 3) * 130 + u] = kv.w;
        float4 vs = make_float4(vv.x * sw, vv.y * sw, vv.z * sw, vv.w * sw);
        *(float4*)&vw_s[u * 36 + c] = vs;
    }
    __syncthreads();

    // scores: scT[c][r] = sum_kk q[r][kk]*k[c][kk]
    // microtile: 8 rows (reg-dup q) x 8 cols (4 natural k pairs)
    {
        int rx = tid & 15, ry = tid >> 4;   // cols 2rx+32j, rows 8ry..+7
        u64 acc[8][4];
#pragma unroll
        for (int i = 0; i < 8; i++)
#pragma unroll
            for (int j = 0; j < 4; j++) acc[i][j] = 0ull;
#pragma unroll
        for (int kk = 0; kk < 32; kk++) {
            u64 qd[8], kp[4];
#pragma unroll
            for (int p = 0; p < 4; p++) {
                float2 q2 = *(const float2*)&qT_s[kk * 130 + 8 * ry + 2 * p];
                qd[2 * p]     = dupf(q2.x);
                qd[2 * p + 1] = dupf(q2.y);
            }
#pragma unroll
            for (int j = 0; j < 4; j++)
                kp[j] = *(const u64*)&kT_s[kk * 130 + 2 * rx + 32 * j];
#pragma unroll
            for (int i = 0; i < 8; i++)
#pragma unroll
                for (int j = 0; j < 4; j++) FFMA2(acc[i][j], qd[i], kp[j]);
        }
#pragma unroll
        for (int i = 0; i < 8; i++) {
            int r = 8 * ry + i;
#pragma unroll
            for (int j = 0; j < 4; j++) {
                int c0 = 2 * rx + 32 * j;
                scT[c0 * 130 + r]       = f2lo(acc[i][j]);
                scT[(c0 + 1) * 130 + r] = f2hi(acc[i][j]);
            }
        }
    }
    __syncthreads();

    // softmax per row r (scT column r), unnormalized exp; norm folded into rowsc
    if (tid < 128) {
        float mx = -3.4e38f;
#pragma unroll 8
        for (int u = 0; u < 128; u++) mx = fmaxf(mx, scT[u * 130 + tid]);
        float sum = 0.f;
#pragma unroll 8
        for (int u = 0; u < 128; u++) {
            float e = __expf(scT[u * 130 + tid] - mx);
            sum += e; scT[u * 130 + tid] = e;
        }
        rowsc[tid] = sims_s[tid] / sum;
    }
    __syncthreads();

    // out: O[r][c] = sum_u P[r][u]*vw[u][c]
    // microtile: 4 rows (reg-dup P) x 4 cols (2 natural vw pairs)
    {
        int tx2 = tid & 7, ty2 = tid >> 3;   // cols 2tx2+16j, rows 4ty2..+3
        u64 o[4][2];
#pragma unroll
        for (int i = 0; i < 4; i++)
#pragma unroll
            for (int j = 0; j < 2; j++) o[i][j] = 0ull;
#pragma unroll 4
        for (int u = 0; u < 128; u++) {
            u64 pd[4], vp[2];
#pragma unroll
            for (int p = 0; p < 2; p++) {
                float2 p2 = *(const float2*)&scT[u * 130 + 4 * ty2 + 2 * p];
                pd[2 * p]     = dupf(p2.x);
                pd[2 * p + 1] = dupf(p2.y);
            }
#pragma unroll
            for (int j = 0; j < 2; j++)
                vp[j] = *(const u64*)&vw_s[u * 36 + 2 * tx2 + 16 * j];
#pragma unroll
            for (int i = 0; i < 4; i++)
#pragma unroll
                for (int j = 0; j < 2; j++) FFMA2(o[i][j], pd[i], vp[j]);
        }
#pragma unroll
        for (int i = 0; i < 4; i++) {
            int r = 4 * ty2 + i;
            float rs = rowsc[r];
            int n = idx_s[r];
            float* rp = res + ((size_t)b * CC + coff) * HW + n;
#pragma unroll
            for (int j = 0; j < 2; j++) {
                int c0 = 2 * tx2 + 16 * j;
                atomicAdd(rp + (size_t)c0 * HW,       f2lo(o[i][j]) * rs);
                atomicAdd(rp + (size_t)(c0 + 1) * HW, f2hi(o[i][j]) * rs);
            }
        }
    }
}

// ---------------- launch ----------------
extern "C" void kernel_launch(void* const* d_in, const int* in_sizes, int n_in,
                              void* d_out, int out_size) {
    const float* x   = (const float*)d_in[0];
    const float* aff = (const float*)d_in[1];
    const float* lnw = (const float*)d_in[2];
    const float* lnb = (const float*)d_in[3];
    const float* wq  = (const float*)d_in[4];
    const float* wk  = (const float*)d_in[5];
    const float* wv  = (const float*)d_in[6];
    float* out = (float*)d_out;

    cudaFuncSetAttribute(topk_kernel, cudaFuncAttributeMaxDynamicSharedMemorySize, TOPK_SMEM);
    cudaFuncSetAttribute(attn_kernel, cudaFuncAttributeMaxDynamicSharedMemorySize, ATTN_SMEM);

    ln_kernel<<<1024, 256>>>(x, lnw, lnb);
    gemm_kernel<<<dim3(256, 2, 3), 256>>>(wq, wk, wv);
    topk_kernel<<<BB * SS, 256, TOPK_SMEM>>>(aff);
    init_out_kernel<<<dim3(HW / 32, CC / 32, BB), dim3(32, 8)>>>(out);
    attn_kernel<<<dim3(NH, SS, BB), 256, ATTN_SMEM>>>(out);
}

// round 9
// speedup vs baseline: 1.5388x; 1.1093x over previous
#include <cuda_runtime.h>
#include <cuda_bf16.h>
#include <cstdint>

// Problem constants
#define BB 2
#define CC 256
#define HW 16384
#define SS 256
#define TT 128
#define NH 8
#define DH 32
#define SCALE 0.17677669529663689f   // 32^-0.5
#define LN_EPS 1e-5f

typedef unsigned long long u64;

// packed fp32x2 FMA (Blackwell FFMA2) — acc = a*b + acc, lanewise on 2 floats
#define FFMA2(acc, a, b) asm("fma.rn.f32x2 %0, %1, %2, %0;" : "+l"(acc) : "l"(a), "l"(b))

__device__ __forceinline__ float f2lo(u64 v) { return __uint_as_float((unsigned)v); }
__device__ __forceinline__ float f2hi(u64 v) { return __uint_as_float((unsigned)(v >> 32)); }
__device__ __forceinline__ u64 dupf(float v) {
    u64 r; asm("mov.b64 %0, {%1, %1};" : "=l"(r) : "f"(v)); return r;
}

// warp-level bf16 MMA, m16n8k16, fp32 accumulate (baseline PTX, no 'a'-arch needed)
#define MMA_BF16(c0,c1,c2,c3, a0,a1,a2,a3, b0,b1) \
    asm("mma.sync.aligned.m16n8k16.row.col.f32.bf16.bf16.f32 " \
        "{%0,%1,%2,%3}, {%4,%5,%6,%7}, {%8,%9}, {%0,%1,%2,%3};" \
        : "+f"(c0), "+f"(c1), "+f"(c2), "+f"(c3) \
        : "r"(a0), "r"(a1), "r"(a2), "r"(a3), "r"(b0), "r"(b1))

// ---------------- scratch (device globals; no allocation allowed) ----------------
__device__ __nv_bfloat16 g_xh[(size_t)BB * HW * CC];  // LN output hi bf16, [m][c]
__device__ __nv_bfloat16 g_xl[(size_t)BB * HW * CC];  // LN output lo bf16
__device__ __nv_bfloat16 g_wh[3 * CC * CC];           // W hi bf16, [mat][o][c]
__device__ __nv_bfloat16 g_wl[3 * CC * CC];
__device__ float g_qT [(size_t)BB * HW * CC];   // [b][n][o]
__device__ float g_kT [(size_t)BB * HW * CC];
__device__ float g_vT [(size_t)BB * HW * CC];
__device__ float g_sims[(size_t)BB * SS * TT];
__device__ int   g_idx [(size_t)BB * SS * TT];

// ---------------- LayerNorm: x (B,C,H,W) -> split bf16 (B,HW,C) -------------------
__global__ void ln_kernel(const float* __restrict__ x,
                          const float* __restrict__ lnw,
                          const float* __restrict__ lnb) {
    __shared__ float tile[256][33];
    __shared__ float red_s[8][32], red_ss[8][32];
    __shared__ float s_mean[32], s_inv[32];

    int blk = blockIdx.x;            // 1024 blocks, 512 per batch
    int b   = blk >> 9;
    int n0  = (blk & 511) * 32;
    int tid = threadIdx.x;           // 256
    int tn  = tid & 31;
    int cg  = tid >> 5;              // warp id 0..7

    const float* xb = x + (size_t)b * CC * HW;

#pragma unroll 8
    for (int r = 0; r < 32; r++) {
        int c = r * 8 + cg;
        tile[c][tn] = xb[(size_t)c * HW + n0 + tn];
    }
    __syncthreads();

    float s = 0.f, ss = 0.f;
#pragma unroll 8
    for (int j = 0; j < 32; j++) {
        float v = tile[cg * 32 + j][tn];
        s += v; ss += v * v;
    }
    red_s[cg][tn] = s; red_ss[cg][tn] = ss;
    __syncthreads();
    if (cg == 0) {
        float S = 0.f, SSU = 0.f;
#pragma unroll
        for (int j = 0; j < 8; j++) { S += red_s[j][tn]; SSU += red_ss[j][tn]; }
        float m   = S * (1.0f / 256.0f);
        float var = SSU * (1.0f / 256.0f) - m * m;
        s_mean[tn] = m;
        s_inv[tn]  = rsqrtf(var + LN_EPS);
    }
    __syncthreads();

    float wv = lnw[tid], bv = lnb[tid];
    size_t rb = (size_t)(b * HW + n0) * CC + tid;
#pragma unroll 8
    for (int it = 0; it < 32; it++) {
        float v = tile[tid][it];
        float y = (v - s_mean[it]) * s_inv[it] * wv + bv;
        __nv_bfloat16 hi = __float2bfloat16(y);
        g_xh[rb + (size_t)it * CC] = hi;
        g_xl[rb + (size_t)it * CC] = __float2bfloat16(y - __bfloat162float(hi));
    }
}

// ---------------- split weights into bf16 hi/lo -----------------------------------
__global__ void wsplit_kernel(const float* __restrict__ Wq,
                              const float* __restrict__ Wk,
                              const float* __restrict__ Wv) {
    int i = blockIdx.x * 256 + threadIdx.x;        // 0 .. 3*65536-1
    int mat = i >> 16, j = i & 65535;
    const float* W = (mat == 0) ? Wq : ((mat == 1) ? Wk : Wv);
    float f = W[j];
    __nv_bfloat16 hi = __float2bfloat16(f);
    g_wh[i] = hi;
    g_wl[i] = __float2bfloat16(f - __bfloat162float(hi));
}

// ---------------- projection GEMM on HMMA (mma.sync, split-bf16 3-product) --------
// CTA 128x128 (N split by blockIdx.y), 8 warps of 64x32, K=256 in 8 chunks of 32.
#define STRA 40                         // smem row stride (bf16 units)
#define GT_SMEM (4 * 128 * STRA * 2)    // Ah, Al, Bh, Bl tiles

__global__ void __launch_bounds__(256, 1) gemm_tc_kernel() {
    extern __shared__ __nv_bfloat16 sm_bf[];
    __nv_bfloat16* Ah = sm_bf;
    __nv_bfloat16* Al = Ah + 128 * STRA;
    __nv_bfloat16* Bh = Al + 128 * STRA;
    __nv_bfloat16* Bl = Bh + 128 * STRA;

    int mat = blockIdx.z;
    float* Cout = (mat == 0) ? g_qT : ((mat == 1) ? g_kT : g_vT);
    size_t bm = (size_t)blockIdx.x * 128;
    int bn = blockIdx.y * 128;

    int tid = threadIdx.x;
    int wid = tid >> 5, lane = tid & 31;
    int grp = lane >> 2, tig = lane & 3;
    int wm = (wid & 1) * 64, wn = (wid >> 1) * 32;

    const __nv_bfloat16* wh_b = g_wh + (size_t)mat * 65536;
    const __nv_bfloat16* wl_b = g_wl + (size_t)mat * 65536;

    // loader indexing: r = tid>>1 (row), half = tid&1 (16-bf16 half of 32-col chunk)
    int lr = tid >> 1, lh = tid & 1;
    const uint4* pAh = (const uint4*)(g_xh + (bm + lr) * 256 + lh * 16);
    const uint4* pAl = (const uint4*)(g_xl + (bm + lr) * 256 + lh * 16);
    const uint4* pBh = (const uint4*)(wh_b + (size_t)(bn + lr) * 256 + lh * 16);
    const uint4* pBl = (const uint4*)(wl_b + (size_t)(bn + lr) * 256 + lh * 16);
    // smem store offset (bf16 units): row*STRA + half*16 + q*8
    int soff = lr * STRA + lh * 16;

    float acc[4][4][4];   // [mi][ni][reg]
#pragma unroll
    for (int mi = 0; mi < 4; mi++)
#pragma unroll
        for (int ni = 0; ni < 4; ni++)
#pragma unroll
            for (int rgi = 0; rgi < 4; rgi++) acc[mi][ni][rgi] = 0.f;

    // prefetch chunk 0
    uint4 rAh[2], rAl[2], rBh[2], rBl[2];
#pragma unroll
    for (int q = 0; q < 2; q++) {
        rAh[q] = pAh[q]; rAl[q] = pAl[q];
        rBh[q] = pBh[q]; rBl[q] = pBl[q];
    }

#pragma unroll 1
    for (int chunk = 0; chunk < 8; chunk++) {
        // store current chunk regs to smem
#pragma unroll
        for (int q = 0; q < 2; q++) {
            *(uint4*)(Ah + soff + q * 8) = rAh[q];
            *(uint4*)(Al + soff + q * 8) = rAl[q];
            *(uint4*)(Bh + soff + q * 8) = rBh[q];
            *(uint4*)(Bl + soff + q * 8) = rBl[q];
        }
        __syncthreads();

        // issue LDG for next chunk (clamped; overlap with MMA below)
        int nc = (chunk < 7) ? (chunk + 1) : 7;
        int gofs = nc * 4;   // uint4s per 32-col chunk step = 32*2/16 = 4
#pragma unroll
        for (int q = 0; q < 2; q++) {
            rAh[q] = pAh[gofs + q]; rAl[q] = pAl[gofs + q];
            rBh[q] = pBh[gofs + q]; rBl[q] = pBl[gofs + q];
        }

        // compute on smem chunk: 2 k-steps of 16
#pragma unroll
        for (int ks = 0; ks < 32; ks += 16) {
            uint32_t ah[4][4], al[4][4], bh[4][2], bl[4][2];
            int ca = ks + tig * 2;
#pragma unroll
            for (int mi = 0; mi < 4; mi++) {
                int r0 = wm + mi * 16 + grp;
                ah[mi][0] = *(const uint32_t*)(Ah + r0 * STRA + ca);
                ah[mi][1] = *(const uint32_t*)(Ah + (r0 + 8) * STRA + ca);
                ah[mi][2] = *(const uint32_t*)(Ah + r0 * STRA + ca + 8);
                ah[mi][3] = *(const uint32_t*)(Ah + (r0 + 8) * STRA + ca + 8);
                al[mi][0] = *(const uint32_t*)(Al + r0 * STRA + ca);
                al[mi][1] = *(const uint32_t*)(Al + (r0 + 8) * STRA + ca);
                al[mi][2] = *(const uint32_t*)(Al + r0 * STRA + ca + 8);
                al[mi][3] = *(const uint32_t*)(Al + (r0 + 8) * STRA + ca + 8);
            }
#pragma unroll
            for (int ni = 0; ni < 4; ni++) {
                int n0 = wn + ni * 8 + grp;
                bh[ni][0] = *(const uint32_t*)(Bh + n0 * STRA + ca);
                bh[ni][1] = *(const uint32_t*)(Bh + n0 * STRA + ca + 8);
                bl[ni][0] = *(const uint32_t*)(Bl + n0 * STRA + ca);
                bl[ni][1] = *(const uint32_t*)(Bl + n0 * STRA + ca + 8);
            }
#pragma unroll
            for (int mi = 0; mi < 4; mi++)
#pragma unroll
                for (int ni = 0; ni < 4; ni++) {
                    float* c = acc[mi][ni];
                    MMA_BF16(c[0], c[1], c[2], c[3],
                             ah[mi][0], ah[mi][1], ah[mi][2], ah[mi][3],
                             bh[ni][0], bh[ni][1]);
                    MMA_BF16(c[0], c[1], c[2], c[3],
                             ah[mi][0], ah[mi][1], ah[mi][2], ah[mi][3],
                             bl[ni][0], bl[ni][1]);
                    MMA_BF16(c[0], c[1], c[2], c[3],
                             al[mi][0], al[mi][1], al[mi][2], al[mi][3],
                             bh[ni][0], bh[ni][1]);
                }
        }
        __syncthreads();
    }

    // write out: 64x32 region per warp
#pragma unroll
    for (int mi = 0; mi < 4; mi++) {
#pragma unroll
        for (int ni = 0; ni < 4; ni++) {
            float* c = acc[mi][ni];
            size_t row = bm + wm + mi * 16 + grp;
            int col = bn + wn + ni * 8 + tig * 2;
            *(float2*)(Cout + row * 256 + col)       = make_float2(c[0], c[1]);
            *(float2*)(Cout + (row + 8) * 256 + col) = make_float2(c[2], c[3]);
        }
    }
}

// ---------------- top-k: per (b,s) row of 16384, select top-128 (radix select) ----
#define TK_N 16384
#define TOPK_SMEM ((TK_N + 256) * 4)
__global__ void topk_kernel(const float* __restrict__ aff) {
    extern __shared__ unsigned int shm[];
    unsigned int* keys = shm;           // 16384
    unsigned int* hist = shm + TK_N;    // 256
    __shared__ unsigned int s_prefix, s_rem, s_cntgt, s_cnteq;
    __shared__ int eq_idx[128];

    int row = blockIdx.x;
    const float* ap = aff + (size_t)row * TK_N;
    int tid = threadIdx.x;              // 256

    for (int n = tid; n < TK_N; n += 256) {
        unsigned int u = __float_as_uint(ap[n]);
        keys[n] = (u & 0x80000000u) ? ~u : (u | 0x80000000u);
    }
    if (tid == 0) { s_prefix = 0u; s_rem = 128u; s_cntgt = 0u; s_cnteq = 0u; }
    __syncthreads();

    for (int sh = 24; sh >= 0; sh -= 8) {
        hist[tid & 255] = 0u;
        __syncthreads();
        unsigned int pref = s_prefix;
        unsigned int mask = (sh == 24) ? 0u : (0xFFFFFFFFu << (sh + 8));
        for (int n = tid; n < TK_N; n += 256) {
            unsigned int k = keys[n];
            if (((k ^ pref) & mask) == 0u)
                atomicAdd(&hist[(k >> sh) & 0xFF], 1u);
        }
        __syncthreads();
        if (tid == 0) {
            unsigned int rem = s_rem, cum = 0u; int sel = 0;
            for (int bin = 255; bin >= 0; --bin) {
                unsigned int c = hist[bin];
                if (cum + c >= rem) { sel = bin; break; }
                cum += c;
            }
            s_prefix = pref | ((unsigned int)sel << sh);
            s_rem = rem - cum;
        }
        __syncthreads();
    }

    unsigned int thr = s_prefix;
    int take_eq = (int)s_rem;
    int n_gt = 128 - take_eq;

    for (int n = tid; n < TK_N; n += 256) {
        unsigned int k = keys[n];
        if (k > thr) {
            int p = (int)atomicAdd(&s_cntgt, 1u);
            g_idx[(size_t)row * 128 + p]  = n;
            g_sims[(size_t)row * 128 + p] = ap[n];
        } else if (k == thr) {
            int e = (int)atomicAdd(&s_cnteq, 1u);
            if (e < 128) eq_idx[e] = n;
        }
    }
    __syncthreads();
    if (tid == 0) {
        int ne = (int)s_cnteq; if (ne > 128) ne = 128;
        for (int i = 1; i < ne; i++) {
            int v = eq_idx[i]; int j = i - 1;
            while (j >= 0 && eq_idx[j] > v) { eq_idx[j + 1] = eq_idx[j]; j--; }
            eq_idx[j + 1] = v;
        }
        for (int i = 0; i < take_eq; i++) {
            int src = (i < ne) ? i : (ne - 1);
            int n = eq_idx[src];
            g_idx[(size_t)row * 128 + n_gt + i]  = n;
            g_sims[(size_t)row * 128 + n_gt + i] = ap[n];
        }
    }
}

// ---------------- init: out[b,c,n] = vT[b,n,c] (tiled transpose) ----------------
__global__ void init_out_kernel(float* __restrict__ out) {
    __shared__ float t[32][33];
    int n0 = blockIdx.x * 32, c0 = blockIdx.y * 32, b = blockIdx.z;
    int tx = threadIdx.x, ty = threadIdx.y;  // 32 x 8
    const float* vb = g_vT + (size_t)b * HW * CC;
#pragma unroll
    for (int j = ty; j < 32; j += 8)
        t[j][tx] = vb[(size_t)(n0 + j) * CC + c0 + tx];
    __syncthreads();
    float* ob = out + (size_t)b * CC * HW;
#pragma unroll
    for (int j = ty; j < 32; j += 8)
        ob[(size_t)(c0 + j) * HW + n0 + tx] = t[tx][j];
}

// ---------------- attention per (head, s, b) -------------------------------------
#define ATTN_SMEM ((32*130*2 + 128*36 + 128*130 + 128*3) * 4)
__global__ void __launch_bounds__(256, 1) attn_kernel(float* __restrict__ res) {
    extern __shared__ float sm[];
    float* qT_s   = sm;                     // [32][130] kk-major, *SCALE
    float* kT_s   = qT_s + 32 * 130;        // [32][130] kk-major
    float* vw_s   = kT_s + 32 * 130;        // [128][36] row-major, *sims
    float* scT    = vw_s + 128 * 36;        // [128][130]  scT[u][r]
    float* sims_s = scT + 128 * 130;
    float* rowsc  = sims_s + 128;
    int*   idx_s  = (int*)(rowsc + 128);

    int h = blockIdx.x, s = blockIdx.y, b = blockIdx.z;
    int tid = threadIdx.x;              // 256
    int base = ((b << 8) + s) << 7;

    if (tid < 128) {
        idx_s[tid]  = g_idx[base + tid];
        sims_s[tid] = g_sims[base + tid];
    }
    __syncthreads();

    int coff = h * DH;
    for (int i = tid; i < 1024; i += 256) {
        int u = i >> 3, c = (i & 7) * 4;
        size_t off = ((size_t)(b * HW + idx_s[u])) * 256 + coff + c;
        float4 qv = *(const float4*)&g_qT[off];
        float4 kv = *(const float4*)&g_kT[off];
        float4 vv = *(const float4*)&g_vT[off];
        float sw = sims_s[u];
        qT_s[(c + 0) * 130 + u] = qv.x * SCALE;
        qT_s[(c + 1) * 130 + u] = qv.y * SCALE;
        qT_s[(c + 2) * 130 + u] = qv.z * SCALE;
        qT_s[(c + 3) * 130 + u] = qv.w * SCALE;
        kT_s[(c + 0) * 130 + u] = kv.x;
        kT_s[(c + 1) * 130 + u] = kv.y;
        kT_s[(c + 2) * 130 + u] = kv.z;
        kT_s[(c + 3) * 130 + u] = kv.w;
        float4 vs = make_float4(vv.x * sw, vv.y * sw, vv.z * sw, vv.w * sw);
        *(float4*)&vw_s[u * 36 + c] = vs;
    }
    __syncthreads();

    // scores: scT[c][r] = sum_kk q[r][kk]*k[c][kk]
    {
        int rx = tid & 15, ry = tid >> 4;   // cols 2rx+32j, rows 8ry..+7
        u64 acc[8][4];
#pragma unroll
        for (int i = 0; i < 8; i++)
#pragma unroll
            for (int j = 0; j < 4; j++) acc[i][j] = 0ull;
#pragma unroll
        for (int kk = 0; kk < 32; kk++) {
            u64 qd[8], kp[4];
#pragma unroll
            for (int p = 0; p < 4; p++) {
                float2 q2 = *(const float2*)&qT_s[kk * 130 + 8 * ry + 2 * p];
                qd[2 * p]     = dupf(q2.x);
                qd[2 * p + 1] = dupf(q2.y);
            }
#pragma unroll
            for (int j = 0; j < 4; j++)
                kp[j] = *(const u64*)&kT_s[kk * 130 + 2 * rx + 32 * j];
#pragma unroll
            for (int i = 0; i < 8; i++)
#pragma unroll
                for (int j = 0; j < 4; j++) FFMA2(acc[i][j], qd[i], kp[j]);
        }
#pragma unroll
        for (int i = 0; i < 8; i++) {
            int r = 8 * ry + i;
#pragma unroll
            for (int j = 0; j < 4; j++) {
                int c0 = 2 * rx + 32 * j;
                scT[c0 * 130 + r]       = f2lo(acc[i][j]);
                scT[(c0 + 1) * 130 + r] = f2hi(acc[i][j]);
            }
        }
    }
    __syncthreads();

    // softmax per row r (scT column r)
    if (tid < 128) {
        float mx = -3.4e38f;
#pragma unroll 8
        for (int u = 0; u < 128; u++) mx = fmaxf(mx, scT[u * 130 + tid]);
        float sum = 0.f;
#pragma unroll 8
        for (int u = 0; u < 128; u++) {
            float e = __expf(scT[u * 130 + tid] - mx);
            sum += e; scT[u * 130 + tid] = e;
        }
        rowsc[tid] = sims_s[tid] / sum;
    }
    __syncthreads();

    // out: O[r][c] = sum_u P[r][u]*vw[u][c], scale + scatter
    {
        int tx2 = tid & 7, ty2 = tid >> 3;   // cols 2tx2+16j, rows 4ty2..+3
        u64 o[4][2];
#pragma unroll
        for (int i = 0; i < 4; i++)
#pragma unroll
            for (int j = 0; j < 2; j++) o[i][j] = 0ull;
#pragma unroll 4
        for (int u = 0; u < 128; u++) {
            u64 pd[4], vp[2];
#pragma unroll
            for (int p = 0; p < 2; p++) {
                float2 p2 = *(const float2*)&scT[u * 130 + 4 * ty2 + 2 * p];
                pd[2 * p]     = dupf(p2.x);
                pd[2 * p + 1] = dupf(p2.y);
            }
#pragma unroll
            for (int j = 0; j < 2; j++)
                vp[j] = *(const u64*)&vw_s[u * 36 + 2 * tx2 + 16 * j];
#pragma unroll
            for (int i = 0; i < 4; i++)
#pragma unroll
                for (int j = 0; j < 2; j++) FFMA2(o[i][j], pd[i], vp[j]);
        }
#pragma unroll
        for (int i = 0; i < 4; i++) {
            int r = 4 * ty2 + i;
            float rs = rowsc[r];
            int n = idx_s[r];
            float* rp = res + ((size_t)b * CC + coff) * HW + n;
#pragma unroll
            for (int j = 0; j < 2; j++) {
                int c0 = 2 * tx2 + 16 * j;
                atomicAdd(rp + (size_t)c0 * HW,       f2lo(o[i][j]) * rs);
                atomicAdd(rp + (size_t)(c0 + 1) * HW, f2hi(o[i][j]) * rs);
            }
        }
    }
}

// ---------------- launch ----------------
extern "C" void kernel_launch(void* const* d_in, const int* in_sizes, int n_in,
                              void* d_out, int out_size) {
    const float* x   = (const float*)d_in[0];
    const float* aff = (const float*)d_in[1];
    const float* lnw = (const float*)d_in[2];
    const float* lnb = (const float*)d_in[3];
    const float* wq  = (const float*)d_in[4];
    const float* wk  = (const float*)d_in[5];
    const float* wv  = (const float*)d_in[6];
    float* out = (float*)d_out;

    cudaFuncSetAttribute(topk_kernel, cudaFuncAttributeMaxDynamicSharedMemorySize, TOPK_SMEM);
    cudaFuncSetAttribute(attn_kernel, cudaFuncAttributeMaxDynamicSharedMemorySize, ATTN_SMEM);
    cudaFuncSetAttribute(gemm_tc_kernel, cudaFuncAttributeMaxDynamicSharedMemorySize, GT_SMEM);

    ln_kernel<<<1024, 256>>>(x, lnw, lnb);
    wsplit_kernel<<<768, 256>>>(wq, wk, wv);
    gemm_tc_kernel<<<dim3(256, 2, 3), 256, GT_SMEM>>>();
    topk_kernel<<<BB * SS, 256, TOPK_SMEM>>>(aff);
    init_out_kernel<<<dim3(HW / 32, CC / 32, BB), dim3(32, 8)>>>(out);
    attn_kernel<<<dim3(NH, SS, BB), 256, ATTN_SMEM>>>(out);
}

// round 10
// speedup vs baseline: 2.2172x; 1.4409x over previous
#include <cuda_runtime.h>
#include <cuda_bf16.h>
#include <cstdint>

// Problem constants
#define BB 2
#define CC 256
#define HW 16384
#define SS 256
#define TT 128
#define NH 8
#define DH 32
#define SCALE 0.17677669529663689f   // 32^-0.5
#define LN_EPS 1e-5f

typedef unsigned long long u64;

// warp-level bf16 MMA, m16n8k16, fp32 accumulate (baseline PTX)
#define MMA_BF16(c0,c1,c2,c3, a0,a1,a2,a3, b0,b1) \
    asm("mma.sync.aligned.m16n8k16.row.col.f32.bf16.bf16.f32 " \
        "{%0,%1,%2,%3}, {%4,%5,%6,%7}, {%8,%9}, {%0,%1,%2,%3};" \
        : "+f"(c0), "+f"(c1), "+f"(c2), "+f"(c3) \
        : "r"(a0), "r"(a1), "r"(a2), "r"(a3), "r"(b0), "r"(b1))

__device__ __forceinline__ uint32_t pk2(__nv_bfloat16 a, __nv_bfloat16 b) {
    unsigned short ua = *(unsigned short*)&a, ub = *(unsigned short*)&b;
    return (uint32_t)ua | ((uint32_t)ub << 16);
}

// ---------------- scratch (device globals; no allocation allowed) ----------------
__device__ __nv_bfloat16 g_xh[(size_t)BB * HW * CC];  // LN output hi bf16, [m][c]
__device__ __nv_bfloat16 g_xl[(size_t)BB * HW * CC];  // LN output lo bf16
__device__ __nv_bfloat16 g_wh[3 * CC * CC];           // W hi bf16, [mat][o][c]
__device__ __nv_bfloat16 g_wl[3 * CC * CC];
__device__ float g_qT [(size_t)BB * HW * CC];   // [b][n][o]
__device__ float g_kT [(size_t)BB * HW * CC];
__device__ float g_vT [(size_t)BB * HW * CC];
__device__ float g_sims[(size_t)BB * SS * TT];
__device__ int   g_idx [(size_t)BB * SS * TT];

// ---------------- LayerNorm: x (B,C,H,W) -> split bf16 (B,HW,C) -------------------
__global__ void ln_kernel(const float* __restrict__ x,
                          const float* __restrict__ lnw,
                          const float* __restrict__ lnb) {
    __shared__ float tile[256][33];
    __shared__ float red_s[8][32], red_ss[8][32];
    __shared__ float s_mean[32], s_inv[32];

    int blk = blockIdx.x;            // 1024 blocks, 512 per batch
    int b   = blk >> 9;
    int n0  = (blk & 511) * 32;
    int tid = threadIdx.x;           // 256
    int tn  = tid & 31;
    int cg  = tid >> 5;              // warp id 0..7

    const float* xb = x + (size_t)b * CC * HW;

#pragma unroll 8
    for (int r = 0; r < 32; r++) {
        int c = r * 8 + cg;
        tile[c][tn] = xb[(size_t)c * HW + n0 + tn];
    }
    __syncthreads();

    float s = 0.f, ss = 0.f;
#pragma unroll 8
    for (int j = 0; j < 32; j++) {
        float v = tile[cg * 32 + j][tn];
        s += v; ss += v * v;
    }
    red_s[cg][tn] = s; red_ss[cg][tn] = ss;
    __syncthreads();
    if (cg == 0) {
        float S = 0.f, SSU = 0.f;
#pragma unroll
        for (int j = 0; j < 8; j++) { S += red_s[j][tn]; SSU += red_ss[j][tn]; }
        float m   = S * (1.0f / 256.0f);
        float var = SSU * (1.0f / 256.0f) - m * m;
        s_mean[tn] = m;
        s_inv[tn]  = rsqrtf(var + LN_EPS);
    }
    __syncthreads();

    float wv = lnw[tid], bv = lnb[tid];
    size_t rb = (size_t)(b * HW + n0) * CC + tid;
#pragma unroll 8
    for (int it = 0; it < 32; it++) {
        float v = tile[tid][it];
        float y = (v - s_mean[it]) * s_inv[it] * wv + bv;
        __nv_bfloat16 hi = __float2bfloat16(y);
        g_xh[rb + (size_t)it * CC] = hi;
        g_xl[rb + (size_t)it * CC] = __float2bfloat16(y - __bfloat162float(hi));
    }
}

// ---------------- split weights into bf16 hi/lo -----------------------------------
__global__ void wsplit_kernel(const float* __restrict__ Wq,
                              const float* __restrict__ Wk,
                              const float* __restrict__ Wv) {
    int i = blockIdx.x * 256 + threadIdx.x;        // 0 .. 3*65536-1
    int mat = i >> 16, j = i & 65535;
    const float* W = (mat == 0) ? Wq : ((mat == 1) ? Wk : Wv);
    float f = W[j];
    __nv_bfloat16 hi = __float2bfloat16(f);
    g_wh[i] = hi;
    g_wl[i] = __float2bfloat16(f - __bfloat162float(hi));
}

// ---------------- projection GEMM on HMMA (mma.sync, split-bf16 3-product) --------
#define STRA 40                         // smem row stride (bf16 units)
#define GT_SMEM (4 * 128 * STRA * 2)    // Ah, Al, Bh, Bl tiles

__global__ void __launch_bounds__(256, 1) gemm_tc_kernel() {
    extern __shared__ __nv_bfloat16 sm_bf[];
    __nv_bfloat16* Ah = sm_bf;
    __nv_bfloat16* Al = Ah + 128 * STRA;
    __nv_bfloat16* Bh = Al + 128 * STRA;
    __nv_bfloat16* Bl = Bh + 128 * STRA;

    int mat = blockIdx.z;
    float* Cout = (mat == 0) ? g_qT : ((mat == 1) ? g_kT : g_vT);
    size_t bm = (size_t)blockIdx.x * 128;
    int bn = blockIdx.y * 128;

    int tid = threadIdx.x;
    int wid = tid >> 5, lane = tid & 31;
    int grp = lane >> 2, tig = lane & 3;
    int wm = (wid & 1) * 64, wn = (wid >> 1) * 32;

    const __nv_bfloat16* wh_b = g_wh + (size_t)mat * 65536;
    const __nv_bfloat16* wl_b = g_wl + (size_t)mat * 65536;

    int lr = tid >> 1, lh = tid & 1;
    const uint4* pAh = (const uint4*)(g_xh + (bm + lr) * 256 + lh * 16);
    const uint4* pAl = (const uint4*)(g_xl + (bm + lr) * 256 + lh * 16);
    const uint4* pBh = (const uint4*)(wh_b + (size_t)(bn + lr) * 256 + lh * 16);
    const uint4* pBl = (const uint4*)(wl_b + (size_t)(bn + lr) * 256 + lh * 16);
    int soff = lr * STRA + lh * 16;

    float acc[4][4][4];
#pragma unroll
    for (int mi = 0; mi < 4; mi++)
#pragma unroll
        for (int ni = 0; ni < 4; ni++)
#pragma unroll
            for (int rgi = 0; rgi < 4; rgi++) acc[mi][ni][rgi] = 0.f;

    uint4 rAh[2], rAl[2], rBh[2], rBl[2];
#pragma unroll
    for (int q = 0; q < 2; q++) {
        rAh[q] = pAh[q]; rAl[q] = pAl[q];
        rBh[q] = pBh[q]; rBl[q] = pBl[q];
    }

#pragma unroll 1
    for (int chunk = 0; chunk < 8; chunk++) {
#pragma unroll
        for (int q = 0; q < 2; q++) {
            *(uint4*)(Ah + soff + q * 8) = rAh[q];
            *(uint4*)(Al + soff + q * 8) = rAl[q];
            *(uint4*)(Bh + soff + q * 8) = rBh[q];
            *(uint4*)(Bl + soff + q * 8) = rBl[q];
        }
        __syncthreads();

        int nc = (chunk < 7) ? (chunk + 1) : 7;
        int gofs = nc * 4;
#pragma unroll
        for (int q = 0; q < 2; q++) {
            rAh[q] = pAh[gofs + q]; rAl[q] = pAl[gofs + q];
            rBh[q] = pBh[gofs + q]; rBl[q] = pBl[gofs + q];
        }

#pragma unroll
        for (int ks = 0; ks < 32; ks += 16) {
            uint32_t ah[4][4], al[4][4], bh[4][2], bl[4][2];
            int ca = ks + tig * 2;
#pragma unroll
            for (int mi = 0; mi < 4; mi++) {
                int r0 = wm + mi * 16 + grp;
                ah[mi][0] = *(const uint32_t*)(Ah + r0 * STRA + ca);
                ah[mi][1] = *(const uint32_t*)(Ah + (r0 + 8) * STRA + ca);
                ah[mi][2] = *(const uint32_t*)(Ah + r0 * STRA + ca + 8);
                ah[mi][3] = *(const uint32_t*)(Ah + (r0 + 8) * STRA + ca + 8);
                al[mi][0] = *(const uint32_t*)(Al + r0 * STRA + ca);
                al[mi][1] = *(const uint32_t*)(Al + (r0 + 8) * STRA + ca);
                al[mi][2] = *(const uint32_t*)(Al + r0 * STRA + ca + 8);
                al[mi][3] = *(const uint32_t*)(Al + (r0 + 8) * STRA + ca + 8);
            }
#pragma unroll
            for (int ni = 0; ni < 4; ni++) {
                int n0 = wn + ni * 8 + grp;
                bh[ni][0] = *(const uint32_t*)(Bh + n0 * STRA + ca);
                bh[ni][1] = *(const uint32_t*)(Bh + n0 * STRA + ca + 8);
                bl[ni][0] = *(const uint32_t*)(Bl + n0 * STRA + ca);
                bl[ni][1] = *(const uint32_t*)(Bl + n0 * STRA + ca + 8);
            }
#pragma unroll
            for (int mi = 0; mi < 4; mi++)
#pragma unroll
                for (int ni = 0; ni < 4; ni++) {
                    float* c = acc[mi][ni];
                    MMA_BF16(c[0], c[1], c[2], c[3],
                             ah[mi][0], ah[mi][1], ah[mi][2], ah[mi][3],
                             bh[ni][0], bh[ni][1]);
                    MMA_BF16(c[0], c[1], c[2], c[3],
                             ah[mi][0], ah[mi][1], ah[mi][2], ah[mi][3],
                             bl[ni][0], bl[ni][1]);
                    MMA_BF16(c[0], c[1], c[2], c[3],
                             al[mi][0], al[mi][1], al[mi][2], al[mi][3],
                             bh[ni][0], bh[ni][1]);
                }
        }
        __syncthreads();
    }

#pragma unroll
    for (int mi = 0; mi < 4; mi++) {
#pragma unroll
        for (int ni = 0; ni < 4; ni++) {
            float* c = acc[mi][ni];
            size_t row = bm + wm + mi * 16 + grp;
            int col = bn + wn + ni * 8 + tig * 2;
            *(float2*)(Cout + row * 256 + col)       = make_float2(c[0], c[1]);
            *(float2*)(Cout + (row + 8) * 256 + col) = make_float2(c[2], c[3]);
        }
    }
}

// ---------------- top-k: per (b,s) row of 16384, select top-128 (radix select) ----
#define TK_N 16384
#define TOPK_SMEM ((TK_N + 256) * 4)
__global__ void topk_kernel(const float* __restrict__ aff) {
    extern __shared__ unsigned int shm[];
    unsigned int* keys = shm;           // 16384
    unsigned int* hist = shm + TK_N;    // 256
    __shared__ unsigned int s_prefix, s_rem, s_cntgt, s_cnteq;
    __shared__ int eq_idx[128];

    int row = blockIdx.x;
    const float* ap = aff + (size_t)row * TK_N;
    int tid = threadIdx.x;              // 256

    for (int n = tid; n < TK_N; n += 256) {
        unsigned int u = __float_as_uint(ap[n]);
        keys[n] = (u & 0x80000000u) ? ~u : (u | 0x80000000u);
    }
    if (tid == 0) { s_prefix = 0u; s_rem = 128u; s_cntgt = 0u; s_cnteq = 0u; }
    __syncthreads();

    for (int sh = 24; sh >= 0; sh -= 8) {
        hist[tid & 255] = 0u;
        __syncthreads();
        unsigned int pref = s_prefix;
        unsigned int mask = (sh == 24) ? 0u : (0xFFFFFFFFu << (sh + 8));
        for (int n = tid; n < TK_N; n += 256) {
            unsigned int k = keys[n];
            if (((k ^ pref) & mask) == 0u)
                atomicAdd(&hist[(k >> sh) & 0xFF], 1u);
        }
        __syncthreads();
        if (tid == 0) {
            unsigned int rem = s_rem, cum = 0u; int sel = 0;
            for (int bin = 255; bin >= 0; --bin) {
                unsigned int c = hist[bin];
                if (cum + c >= rem) { sel = bin; break; }
                cum += c;
            }
            s_prefix = pref | ((unsigned int)sel << sh);
            s_rem = rem - cum;
        }
        __syncthreads();
    }

    unsigned int thr = s_prefix;
    int take_eq = (int)s_rem;
    int n_gt = 128 - take_eq;

    for (int n = tid; n < TK_N; n += 256) {
        unsigned int k = keys[n];
        if (k > thr) {
            int p = (int)atomicAdd(&s_cntgt, 1u);
            g_idx[(size_t)row * 128 + p]  = n;
            g_sims[(size_t)row * 128 + p] = ap[n];
        } else if (k == thr) {
            int e = (int)atomicAdd(&s_cnteq, 1u);
            if (e < 128) eq_idx[e] = n;
        }
    }
    __syncthreads();
    if (tid == 0) {
        int ne = (int)s_cnteq; if (ne > 128) ne = 128;
        for (int i = 1; i < ne; i++) {
            int v = eq_idx[i]; int j = i - 1;
            while (j >= 0 && eq_idx[j] > v) { eq_idx[j + 1] = eq_idx[j]; j--; }
            eq_idx[j + 1] = v;
        }
        for (int i = 0; i < take_eq; i++) {
            int src = (i < ne) ? i : (ne - 1);
            int n = eq_idx[src];
            g_idx[(size_t)row * 128 + n_gt + i]  = n;
            g_sims[(size_t)row * 128 + n_gt + i] = ap[n];
        }
    }
}

// ---------------- init: out[b,c,n] = vT[b,n,c] (tiled transpose) ----------------
__global__ void init_out_kernel(float* __restrict__ out) {
    __shared__ float t[32][33];
    int n0 = blockIdx.x * 32, c0 = blockIdx.y * 32, b = blockIdx.z;
    int tx = threadIdx.x, ty = threadIdx.y;  // 32 x 8
    const float* vb = g_vT + (size_t)b * HW * CC;
#pragma unroll
    for (int j = ty; j < 32; j += 8)
        t[j][tx] = vb[(size_t)(n0 + j) * CC + c0 + tx];
    __syncthreads();
    float* ob = out + (size_t)b * CC * HW;
#pragma unroll
    for (int j = ty; j < 32; j += 8)
        ob[(size_t)(c0 + j) * HW + n0 + tx] = t[tx][j];
}

// ---------------- attention per (head, s, b) — HMMA split-bf16 --------------------
// smem bf16: qh/ql/kh/kl [128][40], vwh/vwl transposed [32][136]; + sims/idx
#define QSTR 40
#define VSTR 136
#define SM_QH 0
#define SM_QL (SM_QH + 128 * QSTR)
#define SM_KH (SM_QL + 128 * QSTR)
#define SM_KL (SM_KH + 128 * QSTR)
#define SM_VH (SM_KL + 128 * QSTR)
#define SM_VL (SM_VH + 32 * VSTR)
#define SM_BF_END (SM_VL + 32 * VSTR)
#define ATTN_SMEM (SM_BF_END * 2 + 128 * 8)

__global__ void __launch_bounds__(256) attn_kernel(float* __restrict__ res) {
    extern __shared__ __nv_bfloat16 abf[];
    __nv_bfloat16* qh = abf + SM_QH;
    __nv_bfloat16* ql = abf + SM_QL;
    __nv_bfloat16* kh = abf + SM_KH;
    __nv_bfloat16* kl = abf + SM_KL;
    __nv_bfloat16* vh = abf + SM_VH;   // [c][u]
    __nv_bfloat16* vl = abf + SM_VL;
    float* sims_s = (float*)(abf + SM_BF_END);
    int*   idx_s  = (int*)(sims_s + 128);

    int h = blockIdx.x, s = blockIdx.y, b = blockIdx.z;
    int tid = threadIdx.x;              // 256
    int wid = tid >> 5, lane = tid & 31;
    int grp = lane >> 2, tig = lane & 3;
    int wm = wid * 16;
    int base = ((b << 8) + s) << 7;

    if (tid < 128) {
        idx_s[tid]  = g_idx[base + tid];
        sims_s[tid] = g_sims[base + tid];
    }
    __syncthreads();

    int coff = h * DH;
    // gather + convert + split (float4 per 4 channels)
    for (int i = tid; i < 1024; i += 256) {
        int u = i >> 3, c = (i & 7) * 4;
        size_t off = ((size_t)(b * HW + idx_s[u])) * 256 + coff + c;
        float4 qv = *(const float4*)&g_qT[off];
        float4 kv = *(const float4*)&g_kT[off];
        float4 vv = *(const float4*)&g_vT[off];
        float sw = sims_s[u];
        float qa[4] = {qv.x * SCALE, qv.y * SCALE, qv.z * SCALE, qv.w * SCALE};
        float ka[4] = {kv.x, kv.y, kv.z, kv.w};
        float va[4] = {vv.x * sw, vv.y * sw, vv.z * sw, vv.w * sw};
        __nv_bfloat16 qhb[4], klb[4], khb[4], qlb[4];
#pragma unroll
        for (int j = 0; j < 4; j++) {
            qhb[j] = __float2bfloat16(qa[j]);
            qlb[j] = __float2bfloat16(qa[j] - __bfloat162float(qhb[j]));
            khb[j] = __float2bfloat16(ka[j]);
            klb[j] = __float2bfloat16(ka[j] - __bfloat162float(khb[j]));
        }
        *(uint32_t*)&qh[u * QSTR + c]     = pk2(qhb[0], qhb[1]);
        *(uint32_t*)&qh[u * QSTR + c + 2] = pk2(qhb[2], qhb[3]);
        *(uint32_t*)&ql[u * QSTR + c]     = pk2(qlb[0], qlb[1]);
        *(uint32_t*)&ql[u * QSTR + c + 2] = pk2(qlb[2], qlb[3]);
        *(uint32_t*)&kh[u * QSTR + c]     = pk2(khb[0], khb[1]);
        *(uint32_t*)&kh[u * QSTR + c + 2] = pk2(khb[2], khb[3]);
        *(uint32_t*)&kl[u * QSTR + c]     = pk2(klb[0], klb[1]);
        *(uint32_t*)&kl[u * QSTR + c + 2] = pk2(klb[2], klb[3]);
#pragma unroll
        for (int j = 0; j < 4; j++) {
            __nv_bfloat16 vhb = __float2bfloat16(va[j]);
            vh[(c + j) * VSTR + u] = vhb;
            vl[(c + j) * VSTR + u] = __float2bfloat16(va[j] - __bfloat162float(vhb));
        }
    }
    __syncthreads();

    // GEMM1: S[wm+.., 128] = Q·K^T (3-product split), acc[16 n-tiles][4]
    float acc[16][4];
#pragma unroll
    for (int nt = 0; nt < 16; nt++)
#pragma unroll
        for (int rgi = 0; rgi < 4; rgi++) acc[nt][rgi] = 0.f;

#pragma unroll
    for (int ks = 0; ks < 2; ks++) {
        int ca = ks * 16 + tig * 2;
        uint32_t ah0 = *(const uint32_t*)&qh[(wm + grp) * QSTR + ca];
        uint32_t ah1 = *(const uint32_t*)&qh[(wm + grp + 8) * QSTR + ca];
        uint32_t ah2 = *(const uint32_t*)&qh[(wm + grp) * QSTR + ca + 8];
        uint32_t ah3 = *(const uint32_t*)&qh[(wm + grp + 8) * QSTR + ca + 8];
        uint32_t al0 = *(const uint32_t*)&ql[(wm + grp) * QSTR + ca];
        uint32_t al1 = *(const uint32_t*)&ql[(wm + grp + 8) * QSTR + ca];
        uint32_t al2 = *(const uint32_t*)&ql[(wm + grp) * QSTR + ca + 8];
        uint32_t al3 = *(const uint32_t*)&ql[(wm + grp + 8) * QSTR + ca + 8];
#pragma unroll
        for (int nt = 0; nt < 16; nt++) {
            int ro = (nt * 8 + grp) * QSTR + ca;
            uint32_t bh0 = *(const uint32_t*)&kh[ro];
            uint32_t bh1 = *(const uint32_t*)&kh[ro + 8];
            uint32_t bl0 = *(const uint32_t*)&kl[ro];
            uint32_t bl1 = *(const uint32_t*)&kl[ro + 8];
            float* c = acc[nt];
            MMA_BF16(c[0], c[1], c[2], c[3], ah0, ah1, ah2, ah3, bh0, bh1);
            MMA_BF16(c[0], c[1], c[2], c[3], ah0, ah1, ah2, ah3, bl0, bl1);
            MMA_BF16(c[0], c[1], c[2], c[3], al0, al1, al2, al3, bh0, bh1);
        }
    }

    // softmax in registers: rows wm+grp (c0,c1) and wm+grp+8 (c2,c3)
    float mx0 = -3.4e38f, mx1 = -3.4e38f;
#pragma unroll
    for (int nt = 0; nt < 16; nt++) {
        mx0 = fmaxf(mx0, fmaxf(acc[nt][0], acc[nt][1]));
        mx1 = fmaxf(mx1, fmaxf(acc[nt][2], acc[nt][3]));
    }
#pragma unroll
    for (int m = 1; m <= 2; m <<= 1) {
        mx0 = fmaxf(mx0, __shfl_xor_sync(0xffffffffu, mx0, m));
        mx1 = fmaxf(mx1, __shfl_xor_sync(0xffffffffu, mx1, m));
    }
    float sum0 = 0.f, sum1 = 0.f;
#pragma unroll
    for (int nt = 0; nt < 16; nt++) {
        acc[nt][0] = __expf(acc[nt][0] - mx0);
        acc[nt][1] = __expf(acc[nt][1] - mx0);
        acc[nt][2] = __expf(acc[nt][2] - mx1);
        acc[nt][3] = __expf(acc[nt][3] - mx1);
        sum0 += acc[nt][0] + acc[nt][1];
        sum1 += acc[nt][2] + acc[nt][3];
    }
#pragma unroll
    for (int m = 1; m <= 2; m <<= 1) {
        sum0 += __shfl_xor_sync(0xffffffffu, sum0, m);
        sum1 += __shfl_xor_sync(0xffffffffu, sum1, m);
    }

    // GEMM2: O[16 rows][32 c] = P·VW, P from acc regs (split), VW from smem
    float ot[4][4];
#pragma unroll
    for (int nt = 0; nt < 4; nt++)
#pragma unroll
        for (int rgi = 0; rgi < 4; rgi++) ot[nt][rgi] = 0.f;

#pragma unroll
    for (int ks = 0; ks < 8; ks++) {
        float* t0 = acc[2 * ks];
        float* t1 = acc[2 * ks + 1];
        __nv_bfloat16 h00 = __float2bfloat16(t0[0]), h01 = __float2bfloat16(t0[1]);
        __nv_bfloat16 h02 = __float2bfloat16(t0[2]), h03 = __float2bfloat16(t0[3]);
        __nv_bfloat16 h10 = __float2bfloat16(t1[0]), h11 = __float2bfloat16(t1[1]);
        __nv_bfloat16 h12 = __float2bfloat16(t1[2]), h13 = __float2bfloat16(t1[3]);
        uint32_t ah0 = pk2(h00, h01), ah1 = pk2(h02, h03);
        uint32_t ah2 = pk2(h10, h11), ah3 = pk2(h12, h13);
        uint32_t al0 = pk2(__float2bfloat16(t0[0] - __bfloat162float(h00)),
                           __float2bfloat16(t0[1] - __bfloat162float(h01)));
        uint32_t al1 = pk2(__float2bfloat16(t0[2] - __bfloat162float(h02)),
                           __float2bfloat16(t0[3] - __bfloat162float(h03)));
        uint32_t al2 = pk2(__float2bfloat16(t1[0] - __bfloat162float(h10)),
                           __float2bfloat16(t1[1] - __bfloat162float(h11)));
        uint32_t al3 = pk2(__float2bfloat16(t1[2] - __bfloat162float(h12)),
                           __float2bfloat16(t1[3] - __bfloat162float(h13)));
        int ub = ks * 16 + tig * 2;
#pragma unroll
        for (int nt = 0; nt < 4; nt++) {
            int bo = (nt * 8 + grp) * VSTR + ub;
            uint32_t bh0 = *(const uint32_t*)&vh[bo];
            uint32_t bh1 = *(const uint32_t*)&vh[bo + 8];
            uint32_t bl0 = *(const uint32_t*)&vl[bo];
            uint32_t bl1 = *(const uint32_t*)&vl[bo + 8];
            float* c = ot[nt];
            MMA_BF16(c[0], c[1], c[2], c[3], ah0, ah1, ah2, ah3, bh0, bh1);
            MMA_BF16(c[0], c[1], c[2], c[3], ah0, ah1, ah2, ah3, bl0, bl1);
            MMA_BF16(c[0], c[1], c[2], c[3], al0, al1, al2, al3, bh0, bh1);
        }
    }

    // scatter with row scale sims/sum
    {
        int r0 = wm + grp, r1 = wm + grp + 8;
        float rs0 = sims_s[r0] / sum0;
        float rs1 = sims_s[r1] / sum1;
        int n0 = idx_s[r0], n1 = idx_s[r1];
        float* rp = res + ((size_t)b * CC + coff) * HW;
#pragma unroll
        for (int nt = 0; nt < 4; nt++) {
            int c0 = nt * 8 + tig * 2;
            atomicAdd(rp + (size_t)c0 * HW + n0,       ot[nt][0] * rs0);
            atomicAdd(rp + (size_t)(c0 + 1) * HW + n0, ot[nt][1] * rs0);
            atomicAdd(rp + (size_t)c0 * HW + n1,       ot[nt][2] * rs1);
            atomicAdd(rp + (size_t)(c0 + 1) * HW + n1, ot[nt][3] * rs1);
        }
    }
}

// ---------------- launch ----------------
extern "C" void kernel_launch(void* const* d_in, const int* in_sizes, int n_in,
                              void* d_out, int out_size) {
    const float* x   = (const float*)d_in[0];
    const float* aff = (const float*)d_in[1];
    const float* lnw = (const float*)d_in[2];
    const float* lnb = (const float*)d_in[3];
    const float* wq  = (const float*)d_in[4];
    const float* wk  = (const float*)d_in[5];
    const float* wv  = (const float*)d_in[6];
    float* out = (float*)d_out;

    cudaFuncSetAttribute(topk_kernel, cudaFuncAttributeMaxDynamicSharedMemorySize, TOPK_SMEM);
    cudaFuncSetAttribute(attn_kernel, cudaFuncAttributeMaxDynamicSharedMemorySize, ATTN_SMEM);
    cudaFuncSetAttribute(gemm_tc_kernel, cudaFuncAttributeMaxDynamicSharedMemorySize, GT_SMEM);

    ln_kernel<<<1024, 256>>>(x, lnw, lnb);
    wsplit_kernel<<<768, 256>>>(wq, wk, wv);
    gemm_tc_kernel<<<dim3(256, 2, 3), 256, GT_SMEM>>>();
    topk_kernel<<<BB * SS, 256, TOPK_SMEM>>>(aff);
    init_out_kernel<<<dim3(HW / 32, CC / 32, BB), dim3(32, 8)>>>(out);
    attn_kernel<<<dim3(NH, SS, BB), 256, ATTN_SMEM>>>(out);
}

// round 11
// speedup vs baseline: 2.4636x; 1.1112x over previous
#include <cuda_runtime.h>
#include <cuda_bf16.h>
#include <cstdint>

// Problem constants
#define BB 2
#define CC 256
#define HW 16384
#define SS 256
#define TT 128
#define NH 8
#define DH 32
#define SCALE 0.17677669529663689f   // 32^-0.5
#define LN_EPS 1e-5f

typedef unsigned long long u64;

// warp-level bf16 MMA, m16n8k16, fp32 accumulate (baseline PTX)
#define MMA_BF16(c0,c1,c2,c3, a0,a1,a2,a3, b0,b1) \
    asm("mma.sync.aligned.m16n8k16.row.col.f32.bf16.bf16.f32 " \
        "{%0,%1,%2,%3}, {%4,%5,%6,%7}, {%8,%9}, {%0,%1,%2,%3};" \
        : "+f"(c0), "+f"(c1), "+f"(c2), "+f"(c3) \
        : "r"(a0), "r"(a1), "r"(a2), "r"(a3), "r"(b0), "r"(b1))

__device__ __forceinline__ uint32_t pk2(__nv_bfloat16 a, __nv_bfloat16 b) {
    unsigned short ua = *(unsigned short*)&a, ub = *(unsigned short*)&b;
    return (uint32_t)ua | ((uint32_t)ub << 16);
}

// ---------------- scratch (device globals; no allocation allowed) ----------------
__device__ __nv_bfloat16 g_xh[(size_t)BB * HW * CC];  // LN output hi bf16, [m][c]
__device__ __nv_bfloat16 g_xl[(size_t)BB * HW * CC];  // LN output lo bf16
__device__ __nv_bfloat16 g_wh[3 * CC * CC];           // W hi bf16, [mat][o][c]
__device__ __nv_bfloat16 g_wl[3 * CC * CC];
__device__ float g_qT [(size_t)BB * HW * CC];   // [b][n][o]
__device__ float g_kT [(size_t)BB * HW * CC];
__device__ float g_vT [(size_t)BB * HW * CC];
__device__ float g_sims[(size_t)BB * SS * TT];
__device__ int   g_idx [(size_t)BB * SS * TT];

// ---------------- LayerNorm: x (B,C,H,W) -> split bf16 (B,HW,C) -------------------
__global__ void ln_kernel(const float* __restrict__ x,
                          const float* __restrict__ lnw,
                          const float* __restrict__ lnb) {
    __shared__ float tile[256][33];
    __shared__ float red_s[8][32], red_ss[8][32];
    __shared__ float s_mean[32], s_inv[32];

    int blk = blockIdx.x;            // 1024 blocks, 512 per batch
    int b   = blk >> 9;
    int n0  = (blk & 511) * 32;
    int tid = threadIdx.x;           // 256
    int tn  = tid & 31;
    int cg  = tid >> 5;              // warp id 0..7

    const float* xb = x + (size_t)b * CC * HW;

#pragma unroll 8
    for (int r = 0; r < 32; r++) {
        int c = r * 8 + cg;
        tile[c][tn] = xb[(size_t)c * HW + n0 + tn];
    }
    __syncthreads();

    float s = 0.f, ss = 0.f;
#pragma unroll 8
    for (int j = 0; j < 32; j++) {
        float v = tile[cg * 32 + j][tn];
        s += v; ss += v * v;
    }
    red_s[cg][tn] = s; red_ss[cg][tn] = ss;
    __syncthreads();
    if (cg == 0) {
        float S = 0.f, SSU = 0.f;
#pragma unroll
        for (int j = 0; j < 8; j++) { S += red_s[j][tn]; SSU += red_ss[j][tn]; }
        float m   = S * (1.0f / 256.0f);
        float var = SSU * (1.0f / 256.0f) - m * m;
        s_mean[tn] = m;
        s_inv[tn]  = rsqrtf(var + LN_EPS);
    }
    __syncthreads();

    float wv = lnw[tid], bv = lnb[tid];
    size_t rb = (size_t)(b * HW + n0) * CC + tid;
#pragma unroll 8
    for (int it = 0; it < 32; it++) {
        float v = tile[tid][it];
        float y = (v - s_mean[it]) * s_inv[it] * wv + bv;
        __nv_bfloat16 hi = __float2bfloat16(y);
        g_xh[rb + (size_t)it * CC] = hi;
        g_xl[rb + (size_t)it * CC] = __float2bfloat16(y - __bfloat162float(hi));
    }
}

// ---------------- split weights into bf16 hi/lo -----------------------------------
__global__ void wsplit_kernel(const float* __restrict__ Wq,
                              const float* __restrict__ Wk,
                              const float* __restrict__ Wv) {
    int i = blockIdx.x * 256 + threadIdx.x;        // 0 .. 3*65536-1
    int mat = i >> 16, j = i & 65535;
    const float* W = (mat == 0) ? Wq : ((mat == 1) ? Wk : Wv);
    float f = W[j];
    __nv_bfloat16 hi = __float2bfloat16(f);
    g_wh[i] = hi;
    g_wl[i] = __float2bfloat16(f - __bfloat162float(hi));
}

// ---------------- projection GEMM on HMMA (mma.sync, split-bf16 3-product) --------
// mat==2 additionally writes V transposed into out[b][c][n] (replaces init_out).
#define STRA 40                         // smem row stride (bf16 units)
#define GT_SMEM (4 * 128 * STRA * 2)    // Ah, Al, Bh, Bl tiles

__global__ void __launch_bounds__(256, 1) gemm_tc_kernel(float* __restrict__ out) {
    extern __shared__ __nv_bfloat16 sm_bf[];
    __nv_bfloat16* Ah = sm_bf;
    __nv_bfloat16* Al = Ah + 128 * STRA;
    __nv_bfloat16* Bh = Al + 128 * STRA;
    __nv_bfloat16* Bl = Bh + 128 * STRA;

    int mat = blockIdx.z;
    float* Cout = (mat == 0) ? g_qT : ((mat == 1) ? g_kT : g_vT);
    size_t bm = (size_t)blockIdx.x * 128;
    int bn = blockIdx.y * 128;

    int tid = threadIdx.x;
    int wid = tid >> 5, lane = tid & 31;
    int grp = lane >> 2, tig = lane & 3;
    int wm = (wid & 1) * 64, wn = (wid >> 1) * 32;

    const __nv_bfloat16* wh_b = g_wh + (size_t)mat * 65536;
    const __nv_bfloat16* wl_b = g_wl + (size_t)mat * 65536;

    int lr = tid >> 1, lh = tid & 1;
    const uint4* pAh = (const uint4*)(g_xh + (bm + lr) * 256 + lh * 16);
    const uint4* pAl = (const uint4*)(g_xl + (bm + lr) * 256 + lh * 16);
    const uint4* pBh = (const uint4*)(wh_b + (size_t)(bn + lr) * 256 + lh * 16);
    const uint4* pBl = (const uint4*)(wl_b + (size_t)(bn + lr) * 256 + lh * 16);
    int soff = lr * STRA + lh * 16;

    float acc[4][4][4];
#pragma unroll
    for (int mi = 0; mi < 4; mi++)
#pragma unroll
        for (int ni = 0; ni < 4; ni++)
#pragma unroll
            for (int rgi = 0; rgi < 4; rgi++) acc[mi][ni][rgi] = 0.f;

    uint4 rAh[2], rAl[2], rBh[2], rBl[2];
#pragma unroll
    for (int q = 0; q < 2; q++) {
        rAh[q] = pAh[q]; rAl[q] = pAl[q];
        rBh[q] = pBh[q]; rBl[q] = pBl[q];
    }

#pragma unroll 1
    for (int chunk = 0; chunk < 8; chunk++) {
#pragma unroll
        for (int q = 0; q < 2; q++) {
            *(uint4*)(Ah + soff + q * 8) = rAh[q];
            *(uint4*)(Al + soff + q * 8) = rAl[q];
            *(uint4*)(Bh + soff + q * 8) = rBh[q];
            *(uint4*)(Bl + soff + q * 8) = rBl[q];
        }
        __syncthreads();

        int nc = (chunk < 7) ? (chunk + 1) : 7;
        int gofs = nc * 4;
#pragma unroll
        for (int q = 0; q < 2; q++) {
            rAh[q] = pAh[gofs + q]; rAl[q] = pAl[gofs + q];
            rBh[q] = pBh[gofs + q]; rBl[q] = pBl[gofs + q];
        }

#pragma unroll
        for (int ks = 0; ks < 32; ks += 16) {
            uint32_t ah[4][4], al[4][4], bh[4][2], bl[4][2];
            int ca = ks + tig * 2;
#pragma unroll
            for (int mi = 0; mi < 4; mi++) {
                int r0 = wm + mi * 16 + grp;
                ah[mi][0] = *(const uint32_t*)(Ah + r0 * STRA + ca);
                ah[mi][1] = *(const uint32_t*)(Ah + (r0 + 8) * STRA + ca);
                ah[mi][2] = *(const uint32_t*)(Ah + r0 * STRA + ca + 8);
                ah[mi][3] = *(const uint32_t*)(Ah + (r0 + 8) * STRA + ca + 8);
                al[mi][0] = *(const uint32_t*)(Al + r0 * STRA + ca);
                al[mi][1] = *(const uint32_t*)(Al + (r0 + 8) * STRA + ca);
                al[mi][2] = *(const uint32_t*)(Al + r0 * STRA + ca + 8);
                al[mi][3] = *(const uint32_t*)(Al + (r0 + 8) * STRA + ca + 8);
            }
#pragma unroll
            for (int ni = 0; ni < 4; ni++) {
                int n0 = wn + ni * 8 + grp;
                bh[ni][0] = *(const uint32_t*)(Bh + n0 * STRA + ca);
                bh[ni][1] = *(const uint32_t*)(Bh + n0 * STRA + ca + 8);
                bl[ni][0] = *(const uint32_t*)(Bl + n0 * STRA + ca);
                bl[ni][1] = *(const uint32_t*)(Bl + n0 * STRA + ca + 8);
            }
#pragma unroll
            for (int mi = 0; mi < 4; mi++)
#pragma unroll
                for (int ni = 0; ni < 4; ni++) {
                    float* c = acc[mi][ni];
                    MMA_BF16(c[0], c[1], c[2], c[3],
                             ah[mi][0], ah[mi][1], ah[mi][2], ah[mi][3],
                             bh[ni][0], bh[ni][1]);
                    MMA_BF16(c[0], c[1], c[2], c[3],
                             ah[mi][0], ah[mi][1], ah[mi][2], ah[mi][3],
                             bl[ni][0], bl[ni][1]);
                    MMA_BF16(c[0], c[1], c[2], c[3],
                             al[mi][0], al[mi][1], al[mi][2], al[mi][3],
                             bh[ni][0], bh[ni][1]);
                }
        }
        __syncthreads();
    }

#pragma unroll
    for (int mi = 0; mi < 4; mi++) {
#pragma unroll
        for (int ni = 0; ni < 4; ni++) {
            float* c = acc[mi][ni];
            size_t row = bm + wm + mi * 16 + grp;
            int col = bn + wn + ni * 8 + tig * 2;
            *(float2*)(Cout + row * 256 + col)       = make_float2(c[0], c[1]);
            *(float2*)(Cout + (row + 8) * 256 + col) = make_float2(c[2], c[3]);
        }
    }

    if (mat == 2) {
        // also write out[b][c][n] = v (base value for the scatter-add)
#pragma unroll
        for (int mi = 0; mi < 4; mi++) {
#pragma unroll
            for (int ni = 0; ni < 4; ni++) {
                float* c = acc[mi][ni];
                size_t row0 = bm + wm + mi * 16 + grp;
                size_t row1 = row0 + 8;
                int col = bn + wn + ni * 8 + tig * 2;
                int b0 = (int)(row0 >> 14), n0 = (int)(row0 & 16383);
                int b1 = (int)(row1 >> 14), n1 = (int)(row1 & 16383);
                out[((size_t)b0 * CC + col) * HW + n0]       = c[0];
                out[((size_t)b0 * CC + col + 1) * HW + n0]   = c[1];
                out[((size_t)b1 * CC + col) * HW + n1]       = c[2];
                out[((size_t)b1 * CC + col + 1) * HW + n1]   = c[3];
            }
        }
    }
}

// ---------------- top-k: per (b,s) row of 16384, select top-128 (radix select) ----
// 512 threads, 4-way replicated histogram, parallel suffix-scan bin selection.
#define TK_N 16384
#define TK_THR 512
#define TOPK_SMEM ((TK_N + 1024 + 256) * 4)
__global__ void __launch_bounds__(TK_THR) topk_kernel(const float* __restrict__ aff) {
    extern __shared__ unsigned int shm[];
    unsigned int* keys  = shm;               // 16384
    unsigned int* hist  = shm + TK_N;        // 4 copies x 256
    unsigned int* sscan = hist + 1024;       // 256
    __shared__ unsigned int s_prefix, s_rem, s_cntgt, s_cnteq, s_sel, s_gt;
    __shared__ int eq_idx[128];

    int row = blockIdx.x;
    const float* ap = aff + (size_t)row * TK_N;
    int tid = threadIdx.x;
    int hcp = (tid >> 5) & 3;                // histogram copy = warp % 4

    for (int n = tid; n < TK_N; n += TK_THR) {
        unsigned int u = __float_as_uint(ap[n]);
        keys[n] = (u & 0x80000000u) ? ~u : (u | 0x80000000u);
    }
    if (tid == 0) { s_prefix = 0u; s_rem = 128u; s_cntgt = 0u; s_cnteq = 0u; }
    __syncthreads();

    for (int sh = 24; sh >= 0; sh -= 8) {
        for (int i = tid; i < 1024; i += TK_THR) hist[i] = 0u;
        __syncthreads();
        unsigned int pref = s_prefix, rem = s_rem;
        unsigned int mask = (sh == 24) ? 0u : (0xFFFFFFFFu << (sh + 8));
#pragma unroll 8
        for (int n = tid; n < TK_N; n += TK_THR) {
            unsigned int k = keys[n];
            if (((k ^ pref) & mask) == 0u)
                atomicAdd(&hist[hcp * 256 + ((k >> sh) & 0xFF)], 1u);
        }
        __syncthreads();
        if (tid < 256)
            sscan[tid] = hist[tid] + hist[256 + tid] + hist[512 + tid] + hist[768 + tid];
        __syncthreads();
        // suffix sum: sscan[b] = count of keys with byte >= b (within prefix)
#pragma unroll
        for (int off = 1; off < 256; off <<= 1) {
            unsigned int v = 0u, a = 0u;
            if (tid < 256) { v = sscan[tid]; if (tid + off < 256) a = sscan[tid + off]; }
            __syncthreads();
            if (tid < 256) sscan[tid] = v + a;
            __syncthreads();
        }
        if (tid < 256) {
            unsigned int ge = sscan[tid];
            unsigned int gt = (tid < 255) ? sscan[tid + 1] : 0u;
            if (ge >= rem && gt < rem) { s_sel = (unsigned int)tid; s_gt = gt; }
        }
        __syncthreads();
        if (tid == 0) {
            s_prefix = pref | (s_sel << sh);
            s_rem = rem - s_gt;
        }
        __syncthreads();
    }

    unsigned int thr = s_prefix;
    int take_eq = (int)s_rem;
    int n_gt = 128 - take_eq;

    for (int n = tid; n < TK_N; n += TK_THR) {
        unsigned int k = keys[n];
        if (k > thr) {
            int p = (int)atomicAdd(&s_cntgt, 1u);
            g_idx[(size_t)row * 128 + p]  = n;
            g_sims[(size_t)row * 128 + p] = ap[n];
        } else if (k == thr) {
            int e = (int)atomicAdd(&s_cnteq, 1u);
            if (e < 128) eq_idx[e] = n;
        }
    }
    __syncthreads();
    if (tid == 0) {
        int ne = (int)s_cnteq; if (ne > 128) ne = 128;
        // sort ascending so ties break toward lowest index (matches lax.top_k)
        for (int i = 1; i < ne; i++) {
            int v = eq_idx[i]; int j = i - 1;
            while (j >= 0 && eq_idx[j] > v) { eq_idx[j + 1] = eq_idx[j]; j--; }
            eq_idx[j + 1] = v;
        }
        for (int i = 0; i < take_eq; i++) {
            int src = (i < ne) ? i : (ne - 1);
            int n = eq_idx[src];
            g_idx[(size_t)row * 128 + n_gt + i]  = n;
            g_sims[(size_t)row * 128 + n_gt + i] = ap[n];
        }
    }
}

// ---------------- attention per (head, s, b) — HMMA split-bf16 --------------------
// smem bf16: qh/ql/kh/kl [128][40], vwh/vwl transposed [32][136]; + sims/idx
#define QSTR 40
#define VSTR 136
#define SM_QH 0
#define SM_QL (SM_QH + 128 * QSTR)
#define SM_KH (SM_QL + 128 * QSTR)
#define SM_KL (SM_KH + 128 * QSTR)
#define SM_VH (SM_KL + 128 * QSTR)
#define SM_VL (SM_VH + 32 * VSTR)
#define SM_BF_END (SM_VL + 32 * VSTR)
#define ATTN_SMEM (SM_BF_END * 2 + 128 * 8)

__global__ void __launch_bounds__(256) attn_kernel(float* __restrict__ res) {
    extern __shared__ __nv_bfloat16 abf[];
    __nv_bfloat16* qh = abf + SM_QH;
    __nv_bfloat16* ql = abf + SM_QL;
    __nv_bfloat16* kh = abf + SM_KH;
    __nv_bfloat16* kl = abf + SM_KL;
    __nv_bfloat16* vh = abf + SM_VH;   // [c][u]
    __nv_bfloat16* vl = abf + SM_VL;
    float* sims_s = (float*)(abf + SM_BF_END);
    int*   idx_s  = (int*)(sims_s + 128);

    int h = blockIdx.x, s = blockIdx.y, b = blockIdx.z;
    int tid = threadIdx.x;              // 256
    int wid = tid >> 5, lane = tid & 31;
    int grp = lane >> 2, tig = lane & 3;
    int wm = wid * 16;
    int base = ((b << 8) + s) << 7;

    if (tid < 128) {
        idx_s[tid]  = g_idx[base + tid];
        sims_s[tid] = g_sims[base + tid];
    }
    __syncthreads();

    int coff = h * DH;
    for (int i = tid; i < 1024; i += 256) {
        int u = i >> 3, c = (i & 7) * 4;
        size_t off = ((size_t)(b * HW + idx_s[u])) * 256 + coff + c;
        float4 qv = *(const float4*)&g_qT[off];
        float4 kv = *(const float4*)&g_kT[off];
        float4 vv = *(const float4*)&g_vT[off];
        float sw = sims_s[u];
        float qa[4] = {qv.x * SCALE, qv.y * SCALE, qv.z * SCALE, qv.w * SCALE};
        float ka[4] = {kv.x, kv.y, kv.z, kv.w};
        float va[4] = {vv.x * sw, vv.y * sw, vv.z * sw, vv.w * sw};
        __nv_bfloat16 qhb[4], klb[4], khb[4], qlb[4];
#pragma unroll
        for (int j = 0; j < 4; j++) {
            qhb[j] = __float2bfloat16(qa[j]);
            qlb[j] = __float2bfloat16(qa[j] - __bfloat162float(qhb[j]));
            khb[j] = __float2bfloat16(ka[j]);
            klb[j] = __float2bfloat16(ka[j] - __bfloat162float(khb[j]));
        }
        *(uint32_t*)&qh[u * QSTR + c]     = pk2(qhb[0], qhb[1]);
        *(uint32_t*)&qh[u * QSTR + c + 2] = pk2(qhb[2], qhb[3]);
        *(uint32_t*)&ql[u * QSTR + c]     = pk2(qlb[0], qlb[1]);
        *(uint32_t*)&ql[u * QSTR + c + 2] = pk2(qlb[2], qlb[3]);
        *(uint32_t*)&kh[u * QSTR + c]     = pk2(khb[0], khb[1]);
        *(uint32_t*)&kh[u * QSTR + c + 2] = pk2(khb[2], khb[3]);
        *(uint32_t*)&kl[u * QSTR + c]     = pk2(klb[0], klb[1]);
        *(uint32_t*)&kl[u * QSTR + c + 2] = pk2(klb[2], klb[3]);
#pragma unroll
        for (int j = 0; j < 4; j++) {
            __nv_bfloat16 vhb = __float2bfloat16(va[j]);
            vh[(c + j) * VSTR + u] = vhb;
            vl[(c + j) * VSTR + u] = __float2bfloat16(va[j] - __bfloat162float(vhb));
        }
    }
    __syncthreads();

    // GEMM1: S[wm+.., 128] = Q·K^T (3-product split), acc[16 n-tiles][4]
    float acc[16][4];
#pragma unroll
    for (int nt = 0; nt < 16; nt++)
#pragma unroll
        for (int rgi = 0; rgi < 4; rgi++) acc[nt][rgi] = 0.f;

#pragma unroll
    for (int ks = 0; ks < 2; ks++) {
        int ca = ks * 16 + tig * 2;
        uint32_t ah0 = *(const uint32_t*)&qh[(wm + grp) * QSTR + ca];
        uint32_t ah1 = *(const uint32_t*)&qh[(wm + grp + 8) * QSTR + ca];
        uint32_t ah2 = *(const uint32_t*)&qh[(wm + grp) * QSTR + ca + 8];
        uint32_t ah3 = *(const uint32_t*)&qh[(wm + grp + 8) * QSTR + ca + 8];
        uint32_t al0 = *(const uint32_t*)&ql[(wm + grp) * QSTR + ca];
        uint32_t al1 = *(const uint32_t*)&ql[(wm + grp + 8) * QSTR + ca];
        uint32_t al2 = *(const uint32_t*)&ql[(wm + grp) * QSTR + ca + 8];
        uint32_t al3 = *(const uint32_t*)&ql[(wm + grp + 8) * QSTR + ca + 8];
#pragma unroll
        for (int nt = 0; nt < 16; nt++) {
            int ro = (nt * 8 + grp) * QSTR + ca;
            uint32_t bh0 = *(const uint32_t*)&kh[ro];
            uint32_t bh1 = *(const uint32_t*)&kh[ro + 8];
            uint32_t bl0 = *(const uint32_t*)&kl[ro];
            uint32_t bl1 = *(const uint32_t*)&kl[ro + 8];
            float* c = acc[nt];
            MMA_BF16(c[0], c[1], c[2], c[3], ah0, ah1, ah2, ah3, bh0, bh1);
            MMA_BF16(c[0], c[1], c[2], c[3], ah0, ah1, ah2, ah3, bl0, bl1);
            MMA_BF16(c[0], c[1], c[2], c[3], al0, al1, al2, al3, bh0, bh1);
        }
    }

    // softmax in registers: rows wm+grp (c0,c1) and wm+grp+8 (c2,c3)
    float mx0 = -3.4e38f, mx1 = -3.4e38f;
#pragma unroll
    for (int nt = 0; nt < 16; nt++) {
        mx0 = fmaxf(mx0, fmaxf(acc[nt][0], acc[nt][1]));
        mx1 = fmaxf(mx1, fmaxf(acc[nt][2], acc[nt][3]));
    }
#pragma unroll
    for (int m = 1; m <= 2; m <<= 1) {
        mx0 = fmaxf(mx0, __shfl_xor_sync(0xffffffffu, mx0, m));
        mx1 = fmaxf(mx1, __shfl_xor_sync(0xffffffffu, mx1, m));
    }
    float sum0 = 0.f, sum1 = 0.f;
#pragma unroll
    for (int nt = 0; nt < 16; nt++) {
        acc[nt][0] = __expf(acc[nt][0] - mx0);
        acc[nt][1] = __expf(acc[nt][1] - mx0);
        acc[nt][2] = __expf(acc[nt][2] - mx1);
        acc[nt][3] = __expf(acc[nt][3] - mx1);
        sum0 += acc[nt][0] + acc[nt][1];
        sum1 += acc[nt][2] + acc[nt][3];
    }
#pragma unroll
    for (int m = 1; m <= 2; m <<= 1) {
        sum0 += __shfl_xor_sync(0xffffffffu, sum0, m);
        sum1 += __shfl_xor_sync(0xffffffffu, sum1, m);
    }

    // GEMM2: O[16 rows][32 c] = P·VW, P from acc regs (split), VW from smem
    float ot[4][4];
#pragma unroll
    for (int nt = 0; nt < 4; nt++)
#pragma unroll
        for (int rgi = 0; rgi < 4; rgi++) ot[nt][rgi] = 0.f;

#pragma unroll
    for (int ks = 0; ks < 8; ks++) {
        float* t0 = acc[2 * ks];
        float* t1 = acc[2 * ks + 1];
        __nv_bfloat16 h00 = __float2bfloat16(t0[0]), h01 = __float2bfloat16(t0[1]);
        __nv_bfloat16 h02 = __float2bfloat16(t0[2]), h03 = __float2bfloat16(t0[3]);
        __nv_bfloat16 h10 = __float2bfloat16(t1[0]), h11 = __float2bfloat16(t1[1]);
        __nv_bfloat16 h12 = __float2bfloat16(t1[2]), h13 = __float2bfloat16(t1[3]);
        uint32_t ah0 = pk2(h00, h01), ah1 = pk2(h02, h03);
        uint32_t ah2 = pk2(h10, h11), ah3 = pk2(h12, h13);
        uint32_t al0 = pk2(__float2bfloat16(t0[0] - __bfloat162float(h00)),
                           __float2bfloat16(t0[1] - __bfloat162float(h01)));
        uint32_t al1 = pk2(__float2bfloat16(t0[2] - __bfloat162float(h02)),
                           __float2bfloat16(t0[3] - __bfloat162float(h03)));
        uint32_t al2 = pk2(__float2bfloat16(t1[0] - __bfloat162float(h10)),
                           __float2bfloat16(t1[1] - __bfloat162float(h11)));
        uint32_t al3 = pk2(__float2bfloat16(t1[2] - __bfloat162float(h12)),
                           __float2bfloat16(t1[3] - __bfloat162float(h13)));
        int ub = ks * 16 + tig * 2;
#pragma unroll
        for (int nt = 0; nt < 4; nt++) {
            int bo = (nt * 8 + grp) * VSTR + ub;
            uint32_t bh0 = *(const uint32_t*)&vh[bo];
            uint32_t bh1 = *(const uint32_t*)&vh[bo + 8];
            uint32_t bl0 = *(const uint32_t*)&vl[bo];
            uint32_t bl1 = *(const uint32_t*)&vl[bo + 8];
            float* c = ot[nt];
            MMA_BF16(c[0], c[1], c[2], c[3], ah0, ah1, ah2, ah3, bh0, bh1);
            MMA_BF16(c[0], c[1], c[2], c[3], ah0, ah1, ah2, ah3, bl0, bl1);
            MMA_BF16(c[0], c[1], c[2], c[3], al0, al1, al2, al3, bh0, bh1);
        }
    }

    // scatter with row scale sims/sum
    {
        int r0 = wm + grp, r1 = wm + grp + 8;
        float rs0 = sims_s[r0] / sum0;
        float rs1 = sims_s[r1] / sum1;
        int n0 = idx_s[r0], n1 = idx_s[r1];
        float* rp = res + ((size_t)b * CC + coff) * HW;
#pragma unroll
        for (int nt = 0; nt < 4; nt++) {
            int c0 = nt * 8 + tig * 2;
            atomicAdd(rp + (size_t)c0 * HW + n0,       ot[nt][0] * rs0);
            atomicAdd(rp + (size_t)(c0 + 1) * HW + n0, ot[nt][1] * rs0);
            atomicAdd(rp + (size_t)c0 * HW + n1,       ot[nt][2] * rs1);
            atomicAdd(rp + (size_t)(c0 + 1) * HW + n1, ot[nt][3] * rs1);
        }
    }
}

// ---------------- launch ----------------
extern "C" void kernel_launch(void* const* d_in, const int* in_sizes, int n_in,
                              void* d_out, int out_size) {
    const float* x   = (const float*)d_in[0];
    const float* aff = (const float*)d_in[1];
    const float* lnw = (const float*)d_in[2];
    const float* lnb = (const float*)d_in[3];
    const float* wq  = (const float*)d_in[4];
    const float* wk  = (const float*)d_in[5];
    const float* wv  = (const float*)d_in[6];
    float* out = (float*)d_out;

    cudaFuncSetAttribute(topk_kernel, cudaFuncAttributeMaxDynamicSharedMemorySize, TOPK_SMEM);
    cudaFuncSetAttribute(attn_kernel, cudaFuncAttributeMaxDynamicSharedMemorySize, ATTN_SMEM);
    cudaFuncSetAttribute(gemm_tc_kernel, cudaFuncAttributeMaxDynamicSharedMemorySize, GT_SMEM);

    ln_kernel<<<1024, 256>>>(x, lnw, lnb);
    wsplit_kernel<<<768, 256>>>(wq, wk, wv);
    gemm_tc_kernel<<<dim3(256, 2, 3), 256, GT_SMEM>>>(out);
    topk_kernel<<<BB * SS, TK_THR, TOPK_SMEM>>>(aff);
    attn_kernel<<<dim3(NH, SS, BB), 256, ATTN_SMEM>>>(out);
}